// round 2
// baseline (speedup 1.0000x reference)
#include <cuda_runtime.h>

#define TB 2
#define TT 2048
#define TD 4096
#define TH 32
#define DH 128
#define NTOK (TB*TT)

// Scratch (device globals: allocation-free rule)
__device__ float g_Q[(size_t)NTOK*TD];
__device__ float g_K[(size_t)NTOK*TD];
__device__ float g_V[(size_t)NTOK*TD];
__device__ float g_A[(size_t)NTOK*TD];

// ---------------------------------------------------------------------------
// GEMM: C[m,n] = sum_k A[m,k] * W[n,k]   (both row-major, K contiguous)
// 128x128 tile, BK=16, 256 threads, 8x8 micro-tile (cols strided by 16).
// ---------------------------------------------------------------------------
#define GBM 128
#define GBN 128
#define GBK 16

__global__ __launch_bounds__(256, 2)
void gemm_nt(const float* __restrict__ A, const float* __restrict__ W,
             float* __restrict__ C, int M, int N, int K)
{
    __shared__ float As[GBM][GBK];      // [row][k]
    __shared__ float Bs[GBN][GBK + 1];  // pad to 17: conflict-free br reads

    const int tid = threadIdx.x;
    const int bm  = blockIdx.y * GBM;
    const int bn  = blockIdx.x * GBN;
    const int r0  = (tid >> 4) * 8;   // 8 rows per thread
    const int c0  = tid & 15;         // cols c0 + 16*j, j=0..7

    float acc[8][8];
#pragma unroll
    for (int i = 0; i < 8; i++)
#pragma unroll
        for (int j = 0; j < 8; j++) acc[i][j] = 0.f;

    const int lr = tid >> 2;          // 0..63
    const int lk = (tid & 3) * 4;     // 0,4,8,12

    for (int kt = 0; kt < K; kt += GBK) {
#pragma unroll
        for (int i = 0; i < 2; i++) {
            int r = lr + i * 64;
            float4 a4 = *(const float4*)&A[(size_t)(bm + r) * K + kt + lk];
            *(float4*)&As[r][lk] = a4;
            float4 b4 = *(const float4*)&W[(size_t)(bn + r) * K + kt + lk];
            Bs[r][lk + 0] = b4.x; Bs[r][lk + 1] = b4.y;
            Bs[r][lk + 2] = b4.z; Bs[r][lk + 3] = b4.w;
        }
        __syncthreads();
#pragma unroll
        for (int kk = 0; kk < GBK; kk++) {
            float ar[8], br[8];
#pragma unroll
            for (int i = 0; i < 8; i++) ar[i] = As[r0 + i][kk];
#pragma unroll
            for (int j = 0; j < 8; j++) br[j] = Bs[c0 + 16 * j][kk];
#pragma unroll
            for (int i = 0; i < 8; i++)
#pragma unroll
                for (int j = 0; j < 8; j++)
                    acc[i][j] = fmaf(ar[i], br[j], acc[i][j]);
        }
        __syncthreads();
    }

#pragma unroll
    for (int i = 0; i < 8; i++) {
        float* crow = &C[(size_t)(bm + r0 + i) * N + bn];
#pragma unroll
        for (int j = 0; j < 8; j++) crow[c0 + 16 * j] = acc[i][j];
    }
}

// ---------------------------------------------------------------------------
// RoPE (in-place on Q and K). Layout: row n = (b,t,h), 128 floats each.
// pair j (elems 2j, 2j+1): angle = t * theta^(-m/64), m = (j<32 ? 2j : 2j-64)
// ---------------------------------------------------------------------------
__global__ void rope_kernel(float* __restrict__ Q, float* __restrict__ K)
{
    int idx = blockIdx.x * blockDim.x + threadIdx.x;   // one pair per thread
    const int NROWS = TB * TT * TH;
    int n = idx >> 6;
    int j = idx & 63;
    if (n >= NROWS) return;
    int t = (n >> 5) & (TT - 1);   // n = (b*T + t)*H + h
    int m = (j < 32) ? 2 * j : 2 * j - 64;
    // theta^(-m/64) = exp(-m * ln(20000)/64)
    float freq = __expf(-(float)m * (9.903487552536127f / 64.0f));
    float s, c;
    sincosf((float)t * freq, &s, &c);
    size_t base = (size_t)n * 128 + 2 * j;
    float2 q = *(float2*)&Q[base];
    float2 k = *(float2*)&K[base];
    *(float2*)&Q[base] = make_float2(q.x * c - q.y * s, q.x * s + q.y * c);
    *(float2*)&K[base] = make_float2(k.x * c - k.y * s, k.x * s + k.y * c);
}

// ---------------------------------------------------------------------------
// Flash attention (causal): BM=BN=64, Dh=128, 128 threads (4 warps).
// Thread owns 8 q-rows (r0=(tid/16)*8). S cols: c0+16j (j<4). O cols: 4c0..+3
// and 64+4c0..+3. Softmax state replicated across the 16-lane row group.
// ---------------------------------------------------------------------------
#define SQS 132   // sQ/sK/sV row stride (pad)
#define SPS 68    // sP row stride

__global__ __launch_bounds__(128, 1)
void attn_kernel(const float* __restrict__ Q, const float* __restrict__ K,
                 const float* __restrict__ V, float* __restrict__ O)
{
    extern __shared__ float sm[];
    float* sQ = sm;                    // 64 x 132
    float* sK = sQ + 64 * SQS;         // 64 x 132
    float* sV = sK + 64 * SQS;         // 64 x 132
    float* sP = sV + 64 * SQS;         // 64 x 68

    const int tid = threadIdx.x;
    const int qt  = blockIdx.x;        // q tile (32)
    const int bh  = blockIdx.y;        // b*32 + h (64)
    const int b   = bh >> 5;
    const int h   = bh & 31;
    const int r0  = (tid >> 4) * 8;
    const int c0  = tid & 15;

    const size_t head_base = (size_t)b * TT * TD + (size_t)h * DH;
    const float scale = 0.08838834764831845f;  // 1/sqrt(128)

    // Load Q tile, pre-scaled
#pragma unroll
    for (int i = 0; i < 16; i++) {
        int f4 = tid + i * 128;
        int r  = f4 >> 5;
        int d4 = (f4 & 31) * 4;
        float4 v = *(const float4*)&Q[head_base + (size_t)(qt * 64 + r) * TD + d4];
        v.x *= scale; v.y *= scale; v.z *= scale; v.w *= scale;
        *(float4*)&sQ[r * SQS + d4] = v;
    }

    float o[8][8];
    float mrow[8], lrow[8];
#pragma unroll
    for (int i = 0; i < 8; i++) {
        mrow[i] = -1e30f; lrow[i] = 0.f;
#pragma unroll
        for (int j = 0; j < 8; j++) o[i][j] = 0.f;
    }

    for (int kt = 0; kt <= qt; kt++) {
        __syncthreads();   // protect sK/sV overwrite; first iter: sQ visibility
#pragma unroll
        for (int i = 0; i < 16; i++) {
            int f4 = tid + i * 128;
            int r  = f4 >> 5;
            int d4 = (f4 & 31) * 4;
            size_t g = head_base + (size_t)(kt * 64 + r) * TD + d4;
            *(float4*)&sK[r * SQS + d4] = *(const float4*)&K[g];
            *(float4*)&sV[r * SQS + d4] = *(const float4*)&V[g];
        }
        __syncthreads();

        // S = (Q*scale) @ K^T   (8 rows x 4 cols per thread)
        float s[8][4];
#pragma unroll
        for (int i = 0; i < 8; i++)
#pragma unroll
            for (int j = 0; j < 4; j++) s[i][j] = 0.f;

#pragma unroll 4
        for (int d = 0; d < 128; d += 4) {
            float4 kv[4];
#pragma unroll
            for (int j = 0; j < 4; j++)
                kv[j] = *(float4*)&sK[(c0 + 16 * j) * SQS + d];
#pragma unroll
            for (int i = 0; i < 8; i++) {
                float4 qv = *(float4*)&sQ[(r0 + i) * SQS + d];
#pragma unroll
                for (int j = 0; j < 4; j++) {
                    s[i][j] = fmaf(qv.x, kv[j].x, s[i][j]);
                    s[i][j] = fmaf(qv.y, kv[j].y, s[i][j]);
                    s[i][j] = fmaf(qv.z, kv[j].z, s[i][j]);
                    s[i][j] = fmaf(qv.w, kv[j].w, s[i][j]);
                }
            }
        }

        if (kt == qt) {   // causal mask on diagonal tile
#pragma unroll
            for (int i = 0; i < 8; i++)
#pragma unroll
                for (int j = 0; j < 4; j++)
                    if (c0 + 16 * j > r0 + i) s[i][j] = -1e30f;
        }

        // online softmax (row group = 16 lanes sharing tid>>4)
#pragma unroll
        for (int i = 0; i < 8; i++) {
            float rm = fmaxf(fmaxf(s[i][0], s[i][1]), fmaxf(s[i][2], s[i][3]));
            rm = fmaxf(rm, __shfl_xor_sync(0xffffffffu, rm, 1));
            rm = fmaxf(rm, __shfl_xor_sync(0xffffffffu, rm, 2));
            rm = fmaxf(rm, __shfl_xor_sync(0xffffffffu, rm, 4));
            rm = fmaxf(rm, __shfl_xor_sync(0xffffffffu, rm, 8));
            float mn    = fmaxf(mrow[i], rm);
            float alpha = __expf(mrow[i] - mn);
            float rs = 0.f;
#pragma unroll
            for (int j = 0; j < 4; j++) {
                float p = __expf(s[i][j] - mn);
                sP[(r0 + i) * SPS + c0 + 16 * j] = p;
                rs += p;
            }
            rs += __shfl_xor_sync(0xffffffffu, rs, 1);
            rs += __shfl_xor_sync(0xffffffffu, rs, 2);
            rs += __shfl_xor_sync(0xffffffffu, rs, 4);
            rs += __shfl_xor_sync(0xffffffffu, rs, 8);
            lrow[i] = lrow[i] * alpha + rs;
            mrow[i] = mn;
#pragma unroll
            for (int j = 0; j < 8; j++) o[i][j] *= alpha;
        }
        __syncwarp();   // sP produced/consumed within the same warp's row groups

        // O += P @ V  (8 rows x (4+4) cols per thread)
#pragma unroll 4
        for (int n = 0; n < 64; n++) {
            float4 va = *(float4*)&sV[n * SQS + c0 * 4];
            float4 vb = *(float4*)&sV[n * SQS + 64 + c0 * 4];
#pragma unroll
            for (int i = 0; i < 8; i++) {
                float p = sP[(r0 + i) * SPS + n];
                o[i][0] = fmaf(p, va.x, o[i][0]);
                o[i][1] = fmaf(p, va.y, o[i][1]);
                o[i][2] = fmaf(p, va.z, o[i][2]);
                o[i][3] = fmaf(p, va.w, o[i][3]);
                o[i][4] = fmaf(p, vb.x, o[i][4]);
                o[i][5] = fmaf(p, vb.y, o[i][5]);
                o[i][6] = fmaf(p, vb.z, o[i][6]);
                o[i][7] = fmaf(p, vb.w, o[i][7]);
            }
        }
    }

    // epilogue: divide by l, write [b,t,h,d]
#pragma unroll
    for (int i = 0; i < 8; i++) {
        float inv = 1.0f / lrow[i];
        int t = qt * 64 + r0 + i;
        size_t base = (size_t)(b * TT + t) * TD + (size_t)h * DH;
        float4 wa = make_float4(o[i][0] * inv, o[i][1] * inv, o[i][2] * inv, o[i][3] * inv);
        float4 wb = make_float4(o[i][4] * inv, o[i][5] * inv, o[i][6] * inv, o[i][7] * inv);
        *(float4*)&O[base + c0 * 4]      = wa;
        *(float4*)&O[base + 64 + c0 * 4] = wb;
    }
}

// ---------------------------------------------------------------------------
extern "C" void kernel_launch(void* const* d_in, const int* in_sizes, int n_in,
                              void* d_out, int out_size)
{
    const float* X  = (const float*)d_in[0];
    const float* Wq = (const float*)d_in[1];
    const float* Wk = (const float*)d_in[2];
    const float* Wv = (const float*)d_in[3];
    const float* Wo = (const float*)d_in[4];
    float* out = (float*)d_out;

    float *Qp, *Kp, *Vp, *Ap;
    cudaGetSymbolAddress((void**)&Qp, g_Q);
    cudaGetSymbolAddress((void**)&Kp, g_K);
    cudaGetSymbolAddress((void**)&Vp, g_V);
    cudaGetSymbolAddress((void**)&Ap, g_A);

    const int attn_smem = (3 * 64 * SQS + 64 * SPS) * (int)sizeof(float); // 118784
    cudaFuncSetAttribute(attn_kernel, cudaFuncAttributeMaxDynamicSharedMemorySize,
                         attn_smem);

    dim3 gg(TD / GBN, NTOK / GBM);   // (32, 32)

    gemm_nt<<<gg, 256>>>(X, Wq, Qp, NTOK, TD, TD);
    gemm_nt<<<gg, 256>>>(X, Wk, Kp, NTOK, TD, TD);
    gemm_nt<<<gg, 256>>>(X, Wv, Vp, NTOK, TD, TD);

    const int npairs = TB * TT * TH * 64;   // 8388608
    rope_kernel<<<npairs / 256, 256>>>(Qp, Kp);

    attn_kernel<<<dim3(TT / 64, TB * TH), 128, attn_smem>>>(Qp, Kp, Vp, Ap);

    gemm_nt<<<gg, 256>>>(Ap, Wo, out, NTOK, TD, TD);
}

// round 4
// speedup vs baseline: 2.7189x; 2.7189x over previous
#include <cuda_runtime.h>
#include <cuda_bf16.h>
#include <cstdint>

#define TB 2
#define TT 2048
#define TD 4096
#define TH 32
#define DH 128
#define NTOK (TB*TT)

// ---------------- scratch (device globals: allocation-free rule) ------------
__device__ float g_Q[(size_t)NTOK*TD];
__device__ float g_K[(size_t)NTOK*TD];
__device__ float g_V[(size_t)NTOK*TD];
__device__ float g_A[(size_t)NTOK*TD];

__device__ __nv_bfloat16 g_Xb[(size_t)NTOK*TD], g_Xs[(size_t)NTOK*TD];
__device__ __nv_bfloat16 g_Wqb[(size_t)TD*TD], g_Wqs[(size_t)TD*TD];
__device__ __nv_bfloat16 g_Wkb[(size_t)TD*TD], g_Wks[(size_t)TD*TD];
__device__ __nv_bfloat16 g_Wvb[(size_t)TD*TD], g_Wvs[(size_t)TD*TD];
__device__ __nv_bfloat16 g_Wob[(size_t)TD*TD], g_Wos[(size_t)TD*TD];
__device__ __nv_bfloat16 g_Ab[(size_t)NTOK*TD], g_As[(size_t)NTOK*TD];

// ---------------------------------------------------------------------------
// fp32 -> bf16 (big, small) split:  x ~= big + small, small = bf16(x - big)
// ---------------------------------------------------------------------------
__global__ __launch_bounds__(256)
void split_bf16(const float* __restrict__ x, __nv_bfloat16* __restrict__ hb,
                __nv_bfloat16* __restrict__ hs)
{
    int i = blockIdx.x * blockDim.x + threadIdx.x;   // float4 index
    float4 v = ((const float4*)x)[i];
    __nv_bfloat16 b0 = __float2bfloat16(v.x);
    __nv_bfloat16 b1 = __float2bfloat16(v.y);
    __nv_bfloat16 b2 = __float2bfloat16(v.z);
    __nv_bfloat16 b3 = __float2bfloat16(v.w);
    __nv_bfloat16 s0 = __float2bfloat16(v.x - __bfloat162float(b0));
    __nv_bfloat16 s1 = __float2bfloat16(v.y - __bfloat162float(b1));
    __nv_bfloat16 s2 = __float2bfloat16(v.z - __bfloat162float(b2));
    __nv_bfloat16 s3 = __float2bfloat16(v.w - __bfloat162float(b3));
    __nv_bfloat162* hb2 = (__nv_bfloat162*)hb;
    __nv_bfloat162* hs2 = (__nv_bfloat162*)hs;
    hb2[2*i]   = __nv_bfloat162(b0, b1);
    hb2[2*i+1] = __nv_bfloat162(b2, b3);
    hs2[2*i]   = __nv_bfloat162(s0, s1);
    hs2[2*i+1] = __nv_bfloat162(s2, s3);
}

// ---------------------------------------------------------------------------
// mma.sync bf16x3 GEMM:  C[m,n] = sum_k A[m,k]*W[n,k]
// C = Ab*Wb + Ab*Ws + As*Wb, fp32 accumulators.
// BM=BN=128, BK=64, 256 thr (8 warps 2x4), warp tile 64x32, 2-stage cp.async.
// ---------------------------------------------------------------------------
#define BM 128
#define BN 128
#define BK 64
#define GK 4096
#define GN 4096

#define STAGE  65536
#define OFF_AB 0
#define OFF_AS 16384
#define OFF_BB 32768
#define OFF_BS 49152
#define GEMM_SMEM (2*STAGE)   // 131072

#define SWZ(x) ((x) ^ (((x) >> 3) & 0x70))

__device__ __forceinline__ uint32_t sm_u32(const void* p) {
    uint32_t a;
    asm("{ .reg .u64 t; cvta.to.shared.u64 t, %1; cvt.u32.u64 %0, t; }"
        : "=r"(a) : "l"(p));
    return a;
}
__device__ __forceinline__ void cpasync16(uint32_t dst, const void* src) {
    asm volatile("cp.async.cg.shared.global [%0], [%1], 16;"
                 :: "r"(dst), "l"(src));
}
__device__ __forceinline__ void ldsm_x4(uint32_t* r, uint32_t addr) {
    asm volatile("ldmatrix.sync.aligned.m8n8.x4.shared.b16 {%0,%1,%2,%3}, [%4];"
                 : "=r"(r[0]), "=r"(r[1]), "=r"(r[2]), "=r"(r[3]) : "r"(addr));
}
__device__ __forceinline__ void mma_bf16(float* d, const uint32_t* a,
                                         const uint32_t* b) {
    asm volatile(
        "mma.sync.aligned.m16n8k16.row.col.f32.bf16.bf16.f32 "
        "{%0,%1,%2,%3}, {%4,%5,%6,%7}, {%8,%9}, {%0,%1,%2,%3};"
        : "+f"(d[0]), "+f"(d[1]), "+f"(d[2]), "+f"(d[3])
        : "r"(a[0]), "r"(a[1]), "r"(a[2]), "r"(a[3]), "r"(b[0]), "r"(b[1]));
}

__global__ __launch_bounds__(256, 1)
void gemm_tc(const __nv_bfloat16* __restrict__ Abig,
             const __nv_bfloat16* __restrict__ Asml,
             const __nv_bfloat16* __restrict__ Bbig,
             const __nv_bfloat16* __restrict__ Bsml,
             float* __restrict__ C)
{
    extern __shared__ char smem[];
    const uint32_t sb = sm_u32(smem);
    const int tid = threadIdx.x, wid = tid >> 5, lane = tid & 31;
    const int bm = blockIdx.y * BM, bn = blockIdx.x * BN;
    const int wm = (wid >> 2) * 64;   // warp m offset (0/64)
    const int wn = (wid & 3) * 32;    // warp n offset (0/32/64/96)

    // per-thread load slots: granule id = tid + t*256 ; row = id>>3, g = id&7
    const int lr = tid >> 3;        // rows lr, lr+32, lr+64, lr+96
    const int lg = (tid & 7) * 16;  // byte col within 128B row

    float acc[4][4][4];
#pragma unroll
    for (int i = 0; i < 4; i++)
#pragma unroll
        for (int j = 0; j < 4; j++)
#pragma unroll
            for (int q = 0; q < 4; q++) acc[i][j][q] = 0.f;

    const int nIter = GK / BK;   // 64

    // ---- stage loader ----
    auto load_stage = [&](int s, int c) {
        const int kc = c * BK;
        uint32_t st = sb + s * STAGE;
#pragma unroll
        for (int t = 0; t < 4; t++) {
            int r = lr + t * 32;
            uint32_t so = SWZ((uint32_t)(r * 128) + lg);
            const __nv_bfloat16* ga = Abig + (size_t)(bm + r) * GK + kc;
            const __nv_bfloat16* gs = Asml + (size_t)(bm + r) * GK + kc;
            const __nv_bfloat16* gb = Bbig + (size_t)(bn + r) * GK + kc;
            const __nv_bfloat16* gt = Bsml + (size_t)(bn + r) * GK + kc;
            cpasync16(st + OFF_AB + so, (const char*)ga + lg);
            cpasync16(st + OFF_AS + so, (const char*)gs + lg);
            cpasync16(st + OFF_BB + so, (const char*)gb + lg);
            cpasync16(st + OFF_BS + so, (const char*)gt + lg);
        }
        asm volatile("cp.async.commit_group;");
    };

    load_stage(0, 0);
    load_stage(1, 1);

    // ldmatrix lane addressing
    const int a_row = (lane & 7) + ((lane >> 3) & 1) * 8;   // row within 16
    const int a_kh  = ((lane >> 4) & 1) * 16;               // k half byte off
    const int b_row = (lane & 7) + ((lane >> 4) & 1) * 8;   // row within 16 (2 n-tiles)
    const int b_kh  = ((lane >> 3) & 1) * 16;

    for (int c = 0; c < nIter; c++) {
        if (c + 2 < nIter) asm volatile("cp.async.wait_group 1;");
        else               asm volatile("cp.async.wait_group 0;");
        __syncthreads();

        uint32_t st = sb + (c & 1) * STAGE;
#pragma unroll
        for (int ks = 0; ks < 4; ks++) {
            const uint32_t kb = ks * 32;
            uint32_t ab[4][4], as_[4][4], bb[2][4], bs[2][4];
#pragma unroll
            for (int i = 0; i < 4; i++) {
                int row = wm + i * 16 + a_row;
                uint32_t off = SWZ((uint32_t)(row * 128) + kb + a_kh);
                ldsm_x4(ab[i],  st + OFF_AB + off);
                ldsm_x4(as_[i], st + OFF_AS + off);
            }
#pragma unroll
            for (int jp = 0; jp < 2; jp++) {
                int row = wn + jp * 16 + b_row;
                uint32_t off = SWZ((uint32_t)(row * 128) + kb + b_kh);
                ldsm_x4(bb[jp], st + OFF_BB + off);
                ldsm_x4(bs[jp], st + OFF_BS + off);
            }
#pragma unroll
            for (int i = 0; i < 4; i++)
#pragma unroll
                for (int j = 0; j < 4; j++) {
                    const uint32_t* vb = &bb[j >> 1][(j & 1) * 2];
                    const uint32_t* vs = &bs[j >> 1][(j & 1) * 2];
                    mma_bf16(acc[i][j], ab[i],  vb);   // Ab*Bb
                    mma_bf16(acc[i][j], ab[i],  vs);   // Ab*Bs
                    mma_bf16(acc[i][j], as_[i], vb);   // As*Bb
                }
        }
        __syncthreads();
        if (c + 2 < nIter) load_stage(c & 1, c + 2);
    }

    // epilogue
    const int g  = lane >> 2;
    const int tq = (lane & 3) * 2;
#pragma unroll
    for (int i = 0; i < 4; i++) {
        int row = bm + wm + i * 16 + g;
#pragma unroll
        for (int j = 0; j < 4; j++) {
            int col = bn + wn + j * 8 + tq;
            *(float2*)&C[(size_t)row * GN + col] =
                make_float2(acc[i][j][0], acc[i][j][1]);
            *(float2*)&C[(size_t)(row + 8) * GN + col] =
                make_float2(acc[i][j][2], acc[i][j][3]);
        }
    }
}

// ---------------------------------------------------------------------------
// RoPE (in-place on Q and K).
// ---------------------------------------------------------------------------
__global__ void rope_kernel(float* __restrict__ Q, float* __restrict__ K)
{
    int idx = blockIdx.x * blockDim.x + threadIdx.x;
    const int NROWS = TB * TT * TH;
    int n = idx >> 6;
    int j = idx & 63;
    if (n >= NROWS) return;
    int t = (n >> 5) & (TT - 1);
    int m = (j < 32) ? 2 * j : 2 * j - 64;
    float freq = __expf(-(float)m * (9.903487552536127f / 64.0f));
    float s, c;
    sincosf((float)t * freq, &s, &c);
    size_t base = (size_t)n * 128 + 2 * j;
    float2 q = *(float2*)&Q[base];
    float2 k = *(float2*)&K[base];
    *(float2*)&Q[base] = make_float2(q.x * c - q.y * s, q.x * s + q.y * c);
    *(float2*)&K[base] = make_float2(k.x * c - k.y * s, k.x * s + k.y * c);
}

// ---------------------------------------------------------------------------
// Flash attention (causal), fp32 FFMA — unchanged from passing round.
// ---------------------------------------------------------------------------
#define SQS 132
#define SPS 68

__global__ __launch_bounds__(128, 1)
void attn_kernel(const float* __restrict__ Q, const float* __restrict__ K,
                 const float* __restrict__ V, float* __restrict__ O)
{
    extern __shared__ float sm[];
    float* sQ = sm;
    float* sK = sQ + 64 * SQS;
    float* sV = sK + 64 * SQS;
    float* sP = sV + 64 * SQS;

    const int tid = threadIdx.x;
    const int qt  = blockIdx.x;
    const int bh  = blockIdx.y;
    const int b   = bh >> 5;
    const int h   = bh & 31;
    const int r0  = (tid >> 4) * 8;
    const int c0  = tid & 15;

    const size_t head_base = (size_t)b * TT * TD + (size_t)h * DH;
    const float scale = 0.08838834764831845f;

#pragma unroll
    for (int i = 0; i < 16; i++) {
        int f4 = tid + i * 128;
        int r  = f4 >> 5;
        int d4 = (f4 & 31) * 4;
        float4 v = *(const float4*)&Q[head_base + (size_t)(qt * 64 + r) * TD + d4];
        v.x *= scale; v.y *= scale; v.z *= scale; v.w *= scale;
        *(float4*)&sQ[r * SQS + d4] = v;
    }

    float o[8][8];
    float mrow[8], lrow[8];
#pragma unroll
    for (int i = 0; i < 8; i++) {
        mrow[i] = -1e30f; lrow[i] = 0.f;
#pragma unroll
        for (int j = 0; j < 8; j++) o[i][j] = 0.f;
    }

    for (int kt = 0; kt <= qt; kt++) {
        __syncthreads();
#pragma unroll
        for (int i = 0; i < 16; i++) {
            int f4 = tid + i * 128;
            int r  = f4 >> 5;
            int d4 = (f4 & 31) * 4;
            size_t g = head_base + (size_t)(kt * 64 + r) * TD + d4;
            *(float4*)&sK[r * SQS + d4] = *(const float4*)&K[g];
            *(float4*)&sV[r * SQS + d4] = *(const float4*)&V[g];
        }
        __syncthreads();

        float s[8][4];
#pragma unroll
        for (int i = 0; i < 8; i++)
#pragma unroll
            for (int j = 0; j < 4; j++) s[i][j] = 0.f;

#pragma unroll 4
        for (int d = 0; d < 128; d += 4) {
            float4 kv[4];
#pragma unroll
            for (int j = 0; j < 4; j++)
                kv[j] = *(float4*)&sK[(c0 + 16 * j) * SQS + d];
#pragma unroll
            for (int i = 0; i < 8; i++) {
                float4 qv = *(float4*)&sQ[(r0 + i) * SQS + d];
#pragma unroll
                for (int j = 0; j < 4; j++) {
                    s[i][j] = fmaf(qv.x, kv[j].x, s[i][j]);
                    s[i][j] = fmaf(qv.y, kv[j].y, s[i][j]);
                    s[i][j] = fmaf(qv.z, kv[j].z, s[i][j]);
                    s[i][j] = fmaf(qv.w, kv[j].w, s[i][j]);
                }
            }
        }

        if (kt == qt) {
#pragma unroll
            for (int i = 0; i < 8; i++)
#pragma unroll
                for (int j = 0; j < 4; j++)
                    if (c0 + 16 * j > r0 + i) s[i][j] = -1e30f;
        }

#pragma unroll
        for (int i = 0; i < 8; i++) {
            float rm = fmaxf(fmaxf(s[i][0], s[i][1]), fmaxf(s[i][2], s[i][3]));
            rm = fmaxf(rm, __shfl_xor_sync(0xffffffffu, rm, 1));
            rm = fmaxf(rm, __shfl_xor_sync(0xffffffffu, rm, 2));
            rm = fmaxf(rm, __shfl_xor_sync(0xffffffffu, rm, 4));
            rm = fmaxf(rm, __shfl_xor_sync(0xffffffffu, rm, 8));
            float mn    = fmaxf(mrow[i], rm);
            float alpha = __expf(mrow[i] - mn);
            float rs = 0.f;
#pragma unroll
            for (int j = 0; j < 4; j++) {
                float p = __expf(s[i][j] - mn);
                sP[(r0 + i) * SPS + c0 + 16 * j] = p;
                rs += p;
            }
            rs += __shfl_xor_sync(0xffffffffu, rs, 1);
            rs += __shfl_xor_sync(0xffffffffu, rs, 2);
            rs += __shfl_xor_sync(0xffffffffu, rs, 4);
            rs += __shfl_xor_sync(0xffffffffu, rs, 8);
            lrow[i] = lrow[i] * alpha + rs;
            mrow[i] = mn;
#pragma unroll
            for (int j = 0; j < 8; j++) o[i][j] *= alpha;
        }
        __syncwarp();

#pragma unroll 4
        for (int n = 0; n < 64; n++) {
            float4 va = *(float4*)&sV[n * SQS + c0 * 4];
            float4 vb = *(float4*)&sV[n * SQS + 64 + c0 * 4];
#pragma unroll
            for (int i = 0; i < 8; i++) {
                float p = sP[(r0 + i) * SPS + n];
                o[i][0] = fmaf(p, va.x, o[i][0]);
                o[i][1] = fmaf(p, va.y, o[i][1]);
                o[i][2] = fmaf(p, va.z, o[i][2]);
                o[i][3] = fmaf(p, va.w, o[i][3]);
                o[i][4] = fmaf(p, vb.x, o[i][4]);
                o[i][5] = fmaf(p, vb.y, o[i][5]);
                o[i][6] = fmaf(p, vb.z, o[i][6]);
                o[i][7] = fmaf(p, vb.w, o[i][7]);
            }
        }
    }

#pragma unroll
    for (int i = 0; i < 8; i++) {
        float inv = 1.0f / lrow[i];
        int t = qt * 64 + r0 + i;
        size_t base = (size_t)(b * TT + t) * TD + (size_t)h * DH;
        float4 wa = make_float4(o[i][0] * inv, o[i][1] * inv, o[i][2] * inv, o[i][3] * inv);
        float4 wb = make_float4(o[i][4] * inv, o[i][5] * inv, o[i][6] * inv, o[i][7] * inv);
        *(float4*)&O[base + c0 * 4]      = wa;
        *(float4*)&O[base + 64 + c0 * 4] = wb;
    }
}

// ---------------------------------------------------------------------------
extern "C" void kernel_launch(void* const* d_in, const int* in_sizes, int n_in,
                              void* d_out, int out_size)
{
    const float* X  = (const float*)d_in[0];
    const float* Wq = (const float*)d_in[1];
    const float* Wk = (const float*)d_in[2];
    const float* Wv = (const float*)d_in[3];
    const float* Wo = (const float*)d_in[4];
    float* out = (float*)d_out;

    float *Qp, *Kp, *Vp, *Ap;
    cudaGetSymbolAddress((void**)&Qp, g_Q);
    cudaGetSymbolAddress((void**)&Kp, g_K);
    cudaGetSymbolAddress((void**)&Vp, g_V);
    cudaGetSymbolAddress((void**)&Ap, g_A);
    __nv_bfloat16 *Xb, *Xs, *Wqb, *Wqs, *Wkb, *Wks, *Wvb, *Wvs, *Wob, *Wos, *Ab, *As;
    cudaGetSymbolAddress((void**)&Xb,  g_Xb);  cudaGetSymbolAddress((void**)&Xs,  g_Xs);
    cudaGetSymbolAddress((void**)&Wqb, g_Wqb); cudaGetSymbolAddress((void**)&Wqs, g_Wqs);
    cudaGetSymbolAddress((void**)&Wkb, g_Wkb); cudaGetSymbolAddress((void**)&Wks, g_Wks);
    cudaGetSymbolAddress((void**)&Wvb, g_Wvb); cudaGetSymbolAddress((void**)&Wvs, g_Wvs);
    cudaGetSymbolAddress((void**)&Wob, g_Wob); cudaGetSymbolAddress((void**)&Wos, g_Wos);
    cudaGetSymbolAddress((void**)&Ab,  g_Ab);  cudaGetSymbolAddress((void**)&As,  g_As);

    const int attn_smem = (3 * 64 * SQS + 64 * SPS) * (int)sizeof(float);
    cudaFuncSetAttribute(attn_kernel, cudaFuncAttributeMaxDynamicSharedMemorySize,
                         attn_smem);
    cudaFuncSetAttribute(gemm_tc, cudaFuncAttributeMaxDynamicSharedMemorySize,
                         GEMM_SMEM);

    const int n4 = (int)((size_t)TD * TD / 4);
    split_bf16<<<n4 / 256, 256>>>(X,  Xb,  Xs);
    split_bf16<<<n4 / 256, 256>>>(Wq, Wqb, Wqs);
    split_bf16<<<n4 / 256, 256>>>(Wk, Wkb, Wks);
    split_bf16<<<n4 / 256, 256>>>(Wv, Wvb, Wvs);
    split_bf16<<<n4 / 256, 256>>>(Wo, Wob, Wos);

    dim3 gg(GN / BN, NTOK / BM);   // (32, 32)
    gemm_tc<<<gg, 256, GEMM_SMEM>>>(Xb, Xs, Wqb, Wqs, Qp);
    gemm_tc<<<gg, 256, GEMM_SMEM>>>(Xb, Xs, Wkb, Wks, Kp);
    gemm_tc<<<gg, 256, GEMM_SMEM>>>(Xb, Xs, Wvb, Wvs, Vp);

    const int npairs = TB * TT * TH * 64;
    rope_kernel<<<npairs / 256, 256>>>(Qp, Kp);

    attn_kernel<<<dim3(TT / 64, TB * TH), 128, attn_smem>>>(Qp, Kp, Vp, Ap);

    split_bf16<<<n4 / 256, 256>>>(Ap, Ab, As);
    gemm_tc<<<gg, 256, GEMM_SMEM>>>(Ab, As, Wob, Wos, out);
}

// round 7
// speedup vs baseline: 3.5194x; 1.2944x over previous
#include <cuda_runtime.h>
#include <cuda_bf16.h>
#include <cstdint>

#define TB 2
#define TT 2048
#define TD 4096
#define TH 32
#define DH 128
#define NTOK (TB*TT)

// ---------------- scratch (device globals: allocation-free rule) ------------
__device__ float g_Q[(size_t)NTOK*TD];
__device__ float g_K[(size_t)NTOK*TD];
__device__ float g_V[(size_t)NTOK*TD];
__device__ float g_A[(size_t)NTOK*TD];

__device__ __nv_bfloat16 g_Xb[(size_t)NTOK*TD], g_Xs[(size_t)NTOK*TD];
__device__ __nv_bfloat16 g_Wqb[(size_t)TD*TD], g_Wqs[(size_t)TD*TD];
__device__ __nv_bfloat16 g_Wkb[(size_t)TD*TD], g_Wks[(size_t)TD*TD];
__device__ __nv_bfloat16 g_Wvb[(size_t)TD*TD], g_Wvs[(size_t)TD*TD];
__device__ __nv_bfloat16 g_Wob[(size_t)TD*TD], g_Wos[(size_t)TD*TD];
__device__ __nv_bfloat16 g_Ab[(size_t)NTOK*TD], g_As[(size_t)NTOK*TD];
// After the QKV GEMMs, the Wq/Wk/Wv split buffers are dead -> reuse:
//   Qb<-g_Wqb  Qs<-g_Wqs  Kb<-g_Wkb  Ks<-g_Wks  Vb<-g_Wvb  Vs<-g_Wvs

// ---------------------------------------------------------------------------
// fp32 -> bf16 (big, small) split
// ---------------------------------------------------------------------------
__global__ __launch_bounds__(256)
void split_bf16(const float* __restrict__ x, __nv_bfloat16* __restrict__ hb,
                __nv_bfloat16* __restrict__ hs)
{
    int i = blockIdx.x * blockDim.x + threadIdx.x;
    float4 v = ((const float4*)x)[i];
    __nv_bfloat16 b0 = __float2bfloat16(v.x);
    __nv_bfloat16 b1 = __float2bfloat16(v.y);
    __nv_bfloat16 b2 = __float2bfloat16(v.z);
    __nv_bfloat16 b3 = __float2bfloat16(v.w);
    __nv_bfloat16 s0 = __float2bfloat16(v.x - __bfloat162float(b0));
    __nv_bfloat16 s1 = __float2bfloat16(v.y - __bfloat162float(b1));
    __nv_bfloat16 s2 = __float2bfloat16(v.z - __bfloat162float(b2));
    __nv_bfloat16 s3 = __float2bfloat16(v.w - __bfloat162float(b3));
    __nv_bfloat162* hb2 = (__nv_bfloat162*)hb;
    __nv_bfloat162* hs2 = (__nv_bfloat162*)hs;
    hb2[2*i]   = __nv_bfloat162(b0, b1);
    hb2[2*i+1] = __nv_bfloat162(b2, b3);
    hs2[2*i]   = __nv_bfloat162(s0, s1);
    hs2[2*i+1] = __nv_bfloat162(s2, s3);
}

// ---------------------------------------------------------------------------
// shared helpers
// ---------------------------------------------------------------------------
__device__ __forceinline__ uint32_t sm_u32(const void* p) {
    uint32_t a;
    asm("{ .reg .u64 t; cvta.to.shared.u64 t, %1; cvt.u32.u64 %0, t; }"
        : "=r"(a) : "l"(p));
    return a;
}
__device__ __forceinline__ void cpasync16(uint32_t dst, const void* src) {
    asm volatile("cp.async.cg.shared.global [%0], [%1], 16;"
                 :: "r"(dst), "l"(src));
}
__device__ __forceinline__ void ldsm_x4(uint32_t* r, uint32_t addr) {
    asm volatile("ldmatrix.sync.aligned.m8n8.x4.shared.b16 {%0,%1,%2,%3}, [%4];"
                 : "=r"(r[0]), "=r"(r[1]), "=r"(r[2]), "=r"(r[3]) : "r"(addr));
}
__device__ __forceinline__ void ldsm_x4_t(uint32_t* r, uint32_t addr) {
    asm volatile("ldmatrix.sync.aligned.m8n8.x4.trans.shared.b16 {%0,%1,%2,%3}, [%4];"
                 : "=r"(r[0]), "=r"(r[1]), "=r"(r[2]), "=r"(r[3]) : "r"(addr));
}
__device__ __forceinline__ void mma_bf16(float* d, const uint32_t* a,
                                         const uint32_t* b) {
    asm volatile(
        "mma.sync.aligned.m16n8k16.row.col.f32.bf16.bf16.f32 "
        "{%0,%1,%2,%3}, {%4,%5,%6,%7}, {%8,%9}, {%0,%1,%2,%3};"
        : "+f"(d[0]), "+f"(d[1]), "+f"(d[2]), "+f"(d[3])
        : "r"(a[0]), "r"(a[1]), "r"(a[2]), "r"(a[3]), "r"(b[0]), "r"(b[1]));
}
__device__ __forceinline__ void split_pack(float lo, float hi,
                                           uint32_t& pb, uint32_t& ps) {
    __nv_bfloat16 bl = __float2bfloat16(lo), bh = __float2bfloat16(hi);
    __nv_bfloat162 v(bl, bh);
    pb = *(uint32_t*)&v;
    __nv_bfloat16 sl = __float2bfloat16(lo - __bfloat162float(bl));
    __nv_bfloat16 sh = __float2bfloat16(hi - __bfloat162float(bh));
    __nv_bfloat162 w(sl, sh);
    ps = *(uint32_t*)&w;
}

// ---------------------------------------------------------------------------
// mma.sync bf16x3 GEMM (unchanged, passing): C = A*W^T via Ab*Wb+Ab*Ws+As*Wb
// ---------------------------------------------------------------------------
#define BM 128
#define BN 128
#define BK 64
#define GK 4096
#define GN 4096

#define STAGE  65536
#define OFF_AB 0
#define OFF_AS 16384
#define OFF_BB 32768
#define OFF_BS 49152
#define GEMM_SMEM (2*STAGE)

#define SWZ(x) ((x) ^ (((x) >> 3) & 0x70))

__global__ __launch_bounds__(256, 1)
void gemm_tc(const __nv_bfloat16* __restrict__ Abig,
             const __nv_bfloat16* __restrict__ Asml,
             const __nv_bfloat16* __restrict__ Bbig,
             const __nv_bfloat16* __restrict__ Bsml,
             float* __restrict__ C)
{
    extern __shared__ char smem[];
    const uint32_t sb = sm_u32(smem);
    const int tid = threadIdx.x, wid = tid >> 5, lane = tid & 31;
    const int bm = blockIdx.y * BM, bn = blockIdx.x * BN;
    const int wm = (wid >> 2) * 64;
    const int wn = (wid & 3) * 32;

    const int lr = tid >> 3;
    const int lg = (tid & 7) * 16;

    float acc[4][4][4];
#pragma unroll
    for (int i = 0; i < 4; i++)
#pragma unroll
        for (int j = 0; j < 4; j++)
#pragma unroll
            for (int q = 0; q < 4; q++) acc[i][j][q] = 0.f;

    const int nIter = GK / BK;

    auto load_stage = [&](int s, int c) {
        const int kc = c * BK;
        uint32_t st = sb + s * STAGE;
#pragma unroll
        for (int t = 0; t < 4; t++) {
            int r = lr + t * 32;
            uint32_t so = SWZ((uint32_t)(r * 128) + lg);
            const __nv_bfloat16* ga = Abig + (size_t)(bm + r) * GK + kc;
            const __nv_bfloat16* gs = Asml + (size_t)(bm + r) * GK + kc;
            const __nv_bfloat16* gb = Bbig + (size_t)(bn + r) * GK + kc;
            const __nv_bfloat16* gt = Bsml + (size_t)(bn + r) * GK + kc;
            cpasync16(st + OFF_AB + so, (const char*)ga + lg);
            cpasync16(st + OFF_AS + so, (const char*)gs + lg);
            cpasync16(st + OFF_BB + so, (const char*)gb + lg);
            cpasync16(st + OFF_BS + so, (const char*)gt + lg);
        }
        asm volatile("cp.async.commit_group;");
    };

    load_stage(0, 0);
    load_stage(1, 1);

    const int a_row = (lane & 7) + ((lane >> 3) & 1) * 8;
    const int a_kh  = ((lane >> 4) & 1) * 16;
    const int b_row = (lane & 7) + ((lane >> 4) & 1) * 8;
    const int b_kh  = ((lane >> 3) & 1) * 16;

    for (int c = 0; c < nIter; c++) {
        if (c + 2 < nIter) asm volatile("cp.async.wait_group 1;");
        else               asm volatile("cp.async.wait_group 0;");
        __syncthreads();

        uint32_t st = sb + (c & 1) * STAGE;
#pragma unroll
        for (int ks = 0; ks < 4; ks++) {
            const uint32_t kb = ks * 32;
            uint32_t ab[4][4], as_[4][4], bb[2][4], bs[2][4];
#pragma unroll
            for (int i = 0; i < 4; i++) {
                int row = wm + i * 16 + a_row;
                uint32_t off = SWZ((uint32_t)(row * 128) + kb + a_kh);
                ldsm_x4(ab[i],  st + OFF_AB + off);
                ldsm_x4(as_[i], st + OFF_AS + off);
            }
#pragma unroll
            for (int jp = 0; jp < 2; jp++) {
                int row = wn + jp * 16 + b_row;
                uint32_t off = SWZ((uint32_t)(row * 128) + kb + b_kh);
                ldsm_x4(bb[jp], st + OFF_BB + off);
                ldsm_x4(bs[jp], st + OFF_BS + off);
            }
#pragma unroll
            for (int i = 0; i < 4; i++)
#pragma unroll
                for (int j = 0; j < 4; j++) {
                    const uint32_t* vb = &bb[j >> 1][(j & 1) * 2];
                    const uint32_t* vs = &bs[j >> 1][(j & 1) * 2];
                    mma_bf16(acc[i][j], ab[i],  vb);
                    mma_bf16(acc[i][j], ab[i],  vs);
                    mma_bf16(acc[i][j], as_[i], vb);
                }
        }
        __syncthreads();
        if (c + 2 < nIter) load_stage(c & 1, c + 2);
    }

    const int g  = lane >> 2;
    const int tq = (lane & 3) * 2;
#pragma unroll
    for (int i = 0; i < 4; i++) {
        int row = bm + wm + i * 16 + g;
#pragma unroll
        for (int j = 0; j < 4; j++) {
            int col = bn + wn + j * 8 + tq;
            *(float2*)&C[(size_t)row * GN + col] =
                make_float2(acc[i][j][0], acc[i][j][1]);
            *(float2*)&C[(size_t)(row + 8) * GN + col] =
                make_float2(acc[i][j][2], acc[i][j][3]);
        }
    }
}

// ---------------------------------------------------------------------------
// RoPE + split: reads fp32 Q,K; writes bf16 big/small splits.
// Q is pre-scaled by 1/sqrt(Dh).
// ---------------------------------------------------------------------------
__global__ __launch_bounds__(256)
void rope_split(const float* __restrict__ Q, const float* __restrict__ K,
                __nv_bfloat16* __restrict__ Qb, __nv_bfloat16* __restrict__ Qs,
                __nv_bfloat16* __restrict__ Kb, __nv_bfloat16* __restrict__ Ks)
{
    int idx = blockIdx.x * blockDim.x + threadIdx.x;
    int n = idx >> 6;
    int j = idx & 63;
    int t = (n >> 5) & (TT - 1);
    int m = (j < 32) ? 2 * j : 2 * j - 64;
    float freq = __expf(-(float)m * (9.903487552536127f / 64.0f));
    float s, c;
    sincosf((float)t * freq, &s, &c);
    size_t base = (size_t)n * 128 + 2 * j;
    float2 q = *(float2*)&Q[base];
    float2 k = *(float2*)&K[base];
    const float scale = 0.08838834764831845f;
    float q1 = (q.x * c - q.y * s) * scale, q2 = (q.x * s + q.y * c) * scale;
    float k1 =  k.x * c - k.y * s,          k2 =  k.x * s + k.y * c;

    __nv_bfloat16 qb1 = __float2bfloat16(q1), qb2 = __float2bfloat16(q2);
    __nv_bfloat16 kb1 = __float2bfloat16(k1), kb2 = __float2bfloat16(k2);
    *(__nv_bfloat162*)(Qb + base) = __nv_bfloat162(qb1, qb2);
    *(__nv_bfloat162*)(Kb + base) = __nv_bfloat162(kb1, kb2);
    *(__nv_bfloat162*)(Qs + base) = __nv_bfloat162(
        __float2bfloat16(q1 - __bfloat162float(qb1)),
        __float2bfloat16(q2 - __bfloat162float(qb2)));
    *(__nv_bfloat162*)(Ks + base) = __nv_bfloat162(
        __float2bfloat16(k1 - __bfloat162float(kb1)),
        __float2bfloat16(k2 - __bfloat162float(kb2)));
}

// ---------------------------------------------------------------------------
// Tensor-core flash attention (causal), bf16x3 for QK^T and P*V.
// CTA: (b,h,q-tile of 128 rows), 256 thr (8 warps x 16 q-rows), k-tile 64.
// SMEM rows are 256B (128 d * bf16); swizzle: 16B col c -> c ^ (row&7).
// ---------------------------------------------------------------------------
#define AOFF_QB 0
#define AOFF_QS 32768
#define AOFF_KB 65536
#define AOFF_KS 81920
#define AOFF_VB 98304
#define AOFF_VS 114688
#define ATT_SMEM 131072

#define SWZ256(r, c16) ((uint32_t)((r) * 256 + (((c16) ^ ((r) & 7)) << 4)))

__global__ __launch_bounds__(256, 1)
void attn_tc(const __nv_bfloat16* __restrict__ Qb, const __nv_bfloat16* __restrict__ Qs,
             const __nv_bfloat16* __restrict__ Kb, const __nv_bfloat16* __restrict__ Ks,
             const __nv_bfloat16* __restrict__ Vb, const __nv_bfloat16* __restrict__ Vs,
             float* __restrict__ O)
{
    extern __shared__ char smem[];
    const uint32_t sb = sm_u32(smem);
    const int tid = threadIdx.x, wid = tid >> 5, lane = tid & 31;
    const int qt = blockIdx.x;            // q tile (16)
    const int bh = blockIdx.y;            // b*32+h (64)
    const int b  = bh >> 5, h = bh & 31;
    const size_t head = (size_t)b * TT * TD + (size_t)h * DH;
    const int wm = wid * 16;              // warp q-row offset in tile

    // ---- load Q tile (128 rows x 128 d) big+small ----
#pragma unroll
    for (int i = 0; i < 8; i++) {
        int g = tid + i * 256;            // 0..2047
        int r = g >> 4, c = g & 15;
        const char* src = (const char*)(Qb + head + (size_t)(qt * 128 + r) * TD) + c * 16;
        const char* srs = (const char*)(Qs + head + (size_t)(qt * 128 + r) * TD) + c * 16;
        cpasync16(sb + AOFF_QB + SWZ256(r, c), src);
        cpasync16(sb + AOFF_QS + SWZ256(r, c), srs);
    }
    asm volatile("cp.async.commit_group;");

    // lane fragment addressing (same mapping as gemm_tc, proven)
    const int a_row = (lane & 7) + ((lane >> 3) & 1) * 8;
    const int a_k16 = (lane >> 4) & 1;
    const int b_row = (lane & 7) + ((lane >> 4) & 1) * 8;
    const int b_k16 = (lane >> 3) & 1;
    const int v_row = (lane & 7) + ((lane >> 3) & 1) * 8;
    const int v_c16 = (lane >> 4) & 1;

    float oacc[16][4];
#pragma unroll
    for (int nt = 0; nt < 16; nt++)
#pragma unroll
        for (int q = 0; q < 4; q++) oacc[nt][q] = 0.f;
    float mrow[2] = {-1e30f, -1e30f};
    float lsum[2] = {0.f, 0.f};

    const int q_lo = qt * 128 + wm + (lane >> 2);   // global q of row-half 0

    const int nkt = 2 * qt + 2;
    for (int kt = 0; kt < nkt; kt++) {
        __syncthreads();   // prior iter's smem reads done before overwrite
#pragma unroll
        for (int i = 0; i < 4; i++) {
            int g = tid + i * 256;        // 0..1023
            int r = g >> 4, c = g & 15;
            size_t grow = head + (size_t)(kt * 64 + r) * TD;
            const char* kb_ = (const char*)(Kb + grow) + c * 16;
            const char* ks_ = (const char*)(Ks + grow) + c * 16;
            const char* vb_ = (const char*)(Vb + grow) + c * 16;
            const char* vs_ = (const char*)(Vs + grow) + c * 16;
            uint32_t so = SWZ256(r, c);
            cpasync16(sb + AOFF_KB + so, kb_);
            cpasync16(sb + AOFF_KS + so, ks_);
            cpasync16(sb + AOFF_VB + so, vb_);
            cpasync16(sb + AOFF_VS + so, vs_);
        }
        asm volatile("cp.async.commit_group;");
        asm volatile("cp.async.wait_group 0;");
        __syncthreads();

        // ---- S = Q K^T (bf16x3), S tiles st=0..7 cover 64 keys ----
        float sacc[8][4];
#pragma unroll
        for (int st = 0; st < 8; st++)
#pragma unroll
            for (int q = 0; q < 4; q++) sacc[st][q] = 0.f;

#pragma unroll
        for (int dc = 0; dc < 8; dc++) {
            uint32_t qb_[4], qs_[4];
            uint32_t qoff = SWZ256(wm + a_row, dc * 2 + a_k16);
            ldsm_x4(qb_, sb + AOFF_QB + qoff);
            ldsm_x4(qs_, sb + AOFF_QS + qoff);
#pragma unroll
            for (int ntp = 0; ntp < 4; ntp++) {
                uint32_t kb_[4], ks_[4];
                uint32_t koff = SWZ256(ntp * 16 + b_row, dc * 2 + b_k16);
                ldsm_x4(kb_, sb + AOFF_KB + koff);
                ldsm_x4(ks_, sb + AOFF_KS + koff);
#pragma unroll
                for (int j = 0; j < 2; j++) {
                    float* d = sacc[ntp * 2 + j];
                    mma_bf16(d, qb_, &kb_[2 * j]);
                    mma_bf16(d, qb_, &ks_[2 * j]);
                    mma_bf16(d, qs_, &kb_[2 * j]);
                }
            }
        }

        // ---- causal mask (only diagonal-adjacent k-tiles need it) ----
        if (kt >= 2 * qt) {
#pragma unroll
            for (int st = 0; st < 8; st++) {
                int key0 = kt * 64 + st * 8 + 2 * (lane & 3);
#pragma unroll
                for (int e = 0; e < 2; e++) {
                    if (key0 + e > q_lo)     sacc[st][e]     = -1e30f;
                    if (key0 + e > q_lo + 8) sacc[st][2 + e] = -1e30f;
                }
            }
        }

        // ---- online softmax (rows q_lo, q_lo+8 per lane) ----
        float alpha[2];
#pragma unroll
        for (int hh = 0; hh < 2; hh++) {
            float mx = -1e30f;
#pragma unroll
            for (int st = 0; st < 8; st++)
                mx = fmaxf(mx, fmaxf(sacc[st][2 * hh], sacc[st][2 * hh + 1]));
            mx = fmaxf(mx, __shfl_xor_sync(0xffffffffu, mx, 1));
            mx = fmaxf(mx, __shfl_xor_sync(0xffffffffu, mx, 2));
            float mn = fmaxf(mrow[hh], mx);
            alpha[hh] = __expf(mrow[hh] - mn);
            mrow[hh] = mn;
            float rs = 0.f;
#pragma unroll
            for (int st = 0; st < 8; st++) {
                float p0 = __expf(sacc[st][2 * hh]     - mn);
                float p1 = __expf(sacc[st][2 * hh + 1] - mn);
                sacc[st][2 * hh] = p0; sacc[st][2 * hh + 1] = p1;
                rs += p0 + p1;
            }
            rs += __shfl_xor_sync(0xffffffffu, rs, 1);
            rs += __shfl_xor_sync(0xffffffffu, rs, 2);
            lsum[hh] = lsum[hh] * alpha[hh] + rs;
        }
#pragma unroll
        for (int nt = 0; nt < 16; nt++) {
            oacc[nt][0] *= alpha[0]; oacc[nt][1] *= alpha[0];
            oacc[nt][2] *= alpha[1]; oacc[nt][3] *= alpha[1];
        }

        // ---- O += P V (bf16x3); P frags straight from S accumulators ----
#pragma unroll
        for (int kc = 0; kc < 4; kc++) {
            uint32_t pb[4], ps[4];
            split_pack(sacc[2*kc][0],   sacc[2*kc][1],   pb[0], ps[0]);
            split_pack(sacc[2*kc][2],   sacc[2*kc][3],   pb[1], ps[1]);
            split_pack(sacc[2*kc+1][0], sacc[2*kc+1][1], pb[2], ps[2]);
            split_pack(sacc[2*kc+1][2], sacc[2*kc+1][3], pb[3], ps[3]);
#pragma unroll
            for (int np = 0; np < 8; np++) {
                uint32_t vb_[4], vs_[4];
                uint32_t voff = SWZ256(kc * 16 + v_row, np * 2 + v_c16);
                ldsm_x4_t(vb_, sb + AOFF_VB + voff);
                ldsm_x4_t(vs_, sb + AOFF_VS + voff);
#pragma unroll
                for (int j = 0; j < 2; j++) {
                    float* d = oacc[np * 2 + j];
                    mma_bf16(d, pb, &vb_[2 * j]);
                    mma_bf16(d, pb, &vs_[2 * j]);
                    mma_bf16(d, ps, &vb_[2 * j]);
                }
            }
        }
    }

    // ---- epilogue: O /= l, write [b,t][h*128+d] ----
    float inv0 = 1.0f / lsum[0], inv1 = 1.0f / lsum[1];
    int row0 = b * TT + q_lo;
#pragma unroll
    for (int nt = 0; nt < 16; nt++) {
        int col = h * DH + nt * 8 + 2 * (lane & 3);
        *(float2*)&O[(size_t)row0 * TD + col] =
            make_float2(oacc[nt][0] * inv0, oacc[nt][1] * inv0);
        *(float2*)&O[(size_t)(row0 + 8) * TD + col] =
            make_float2(oacc[nt][2] * inv1, oacc[nt][3] * inv1);
    }
}

// ---------------------------------------------------------------------------
extern "C" void kernel_launch(void* const* d_in, const int* in_sizes, int n_in,
                              void* d_out, int out_size)
{
    const float* X  = (const float*)d_in[0];
    const float* Wq = (const float*)d_in[1];
    const float* Wk = (const float*)d_in[2];
    const float* Wv = (const float*)d_in[3];
    const float* Wo = (const float*)d_in[4];
    float* out = (float*)d_out;

    float *Qp, *Kp, *Vp, *Ap;
    cudaGetSymbolAddress((void**)&Qp, g_Q);
    cudaGetSymbolAddress((void**)&Kp, g_K);
    cudaGetSymbolAddress((void**)&Vp, g_V);
    cudaGetSymbolAddress((void**)&Ap, g_A);
    __nv_bfloat16 *Xb, *Xs, *Wqb, *Wqs, *Wkb, *Wks, *Wvb, *Wvs, *Wob, *Wos, *Ab, *As;
    cudaGetSymbolAddress((void**)&Xb,  g_Xb);  cudaGetSymbolAddress((void**)&Xs,  g_Xs);
    cudaGetSymbolAddress((void**)&Wqb, g_Wqb); cudaGetSymbolAddress((void**)&Wqs, g_Wqs);
    cudaGetSymbolAddress((void**)&Wkb, g_Wkb); cudaGetSymbolAddress((void**)&Wks, g_Wks);
    cudaGetSymbolAddress((void**)&Wvb, g_Wvb); cudaGetSymbolAddress((void**)&Wvs, g_Wvs);
    cudaGetSymbolAddress((void**)&Wob, g_Wob); cudaGetSymbolAddress((void**)&Wos, g_Wos);
    cudaGetSymbolAddress((void**)&Ab,  g_Ab);  cudaGetSymbolAddress((void**)&As,  g_As);

    cudaFuncSetAttribute(gemm_tc, cudaFuncAttributeMaxDynamicSharedMemorySize,
                         GEMM_SMEM);
    cudaFuncSetAttribute(attn_tc, cudaFuncAttributeMaxDynamicSharedMemorySize,
                         ATT_SMEM);

    const int n4 = (int)((size_t)TD * TD / 4);
    split_bf16<<<n4 / 256, 256>>>(X,  Xb,  Xs);
    split_bf16<<<n4 / 256, 256>>>(Wq, Wqb, Wqs);
    split_bf16<<<n4 / 256, 256>>>(Wk, Wkb, Wks);
    split_bf16<<<n4 / 256, 256>>>(Wv, Wvb, Wvs);
    split_bf16<<<n4 / 256, 256>>>(Wo, Wob, Wos);

    dim3 gg(GN / BN, NTOK / BM);
    gemm_tc<<<gg, 256, GEMM_SMEM>>>(Xb, Xs, Wqb, Wqs, Qp);
    gemm_tc<<<gg, 256, GEMM_SMEM>>>(Xb, Xs, Wkb, Wks, Kp);
    gemm_tc<<<gg, 256, GEMM_SMEM>>>(Xb, Xs, Wvb, Wvs, Vp);

    // Wq/Wk/Wv splits are dead now -> reuse as Q/K/V bf16 split buffers
    const int npairs = TB * TT * TH * 64;
    rope_split<<<npairs / 256, 256>>>(Qp, Kp, Wqb, Wqs, Wkb, Wks);
    split_bf16<<<n4 / 256, 256>>>(Vp, Wvb, Wvs);

    attn_tc<<<dim3(TT / 128, TB * TH), 256, ATT_SMEM>>>(
        Wqb, Wqs, Wkb, Wks, Wvb, Wvs, Ap);

    split_bf16<<<n4 / 256, 256>>>(Ap, Ab, As);
    gemm_tc<<<gg, 256, GEMM_SMEM>>>(Ab, As, Wob, Wos, out);
}

// round 10
// speedup vs baseline: 3.5632x; 1.0125x over previous
#include <cuda_runtime.h>
#include <cuda_bf16.h>
#include <cstdint>

#define TB 2
#define TT 2048
#define TD 4096
#define TH 32
#define DH 128
#define NTOK (TB*TT)

// ---------------- scratch (device globals: allocation-free rule) ------------
__device__ float g_Q[(size_t)NTOK*TD];
__device__ float g_K[(size_t)NTOK*TD];
__device__ float g_V[(size_t)NTOK*TD];
__device__ float g_A[(size_t)NTOK*TD];

__device__ __nv_bfloat16 g_Xb[(size_t)NTOK*TD], g_Xs[(size_t)NTOK*TD];
__device__ __nv_bfloat16 g_Wqb[(size_t)TD*TD], g_Wqs[(size_t)TD*TD];
__device__ __nv_bfloat16 g_Wkb[(size_t)TD*TD], g_Wks[(size_t)TD*TD];
__device__ __nv_bfloat16 g_Wvb[(size_t)TD*TD], g_Wvs[(size_t)TD*TD];
__device__ __nv_bfloat16 g_Wob[(size_t)TD*TD], g_Wos[(size_t)TD*TD];
__device__ __nv_bfloat16 g_Ab[(size_t)NTOK*TD], g_As[(size_t)NTOK*TD];
// After the QKV GEMMs, the Wq/Wk/Wv split buffers are dead -> reuse:
//   Qb<-g_Wqb  Qs<-g_Wqs  Kb<-g_Wkb  Ks<-g_Wks  Vb<-g_Wvb  Vs<-g_Wvs

// ---------------------------------------------------------------------------
// fp32 -> bf16 (big, small) split
// ---------------------------------------------------------------------------
__global__ __launch_bounds__(256)
void split_bf16(const float* __restrict__ x, __nv_bfloat16* __restrict__ hb,
                __nv_bfloat16* __restrict__ hs)
{
    int i = blockIdx.x * blockDim.x + threadIdx.x;
    float4 v = ((const float4*)x)[i];
    __nv_bfloat16 b0 = __float2bfloat16(v.x);
    __nv_bfloat16 b1 = __float2bfloat16(v.y);
    __nv_bfloat16 b2 = __float2bfloat16(v.z);
    __nv_bfloat16 b3 = __float2bfloat16(v.w);
    __nv_bfloat16 s0 = __float2bfloat16(v.x - __bfloat162float(b0));
    __nv_bfloat16 s1 = __float2bfloat16(v.y - __bfloat162float(b1));
    __nv_bfloat16 s2 = __float2bfloat16(v.z - __bfloat162float(b2));
    __nv_bfloat16 s3 = __float2bfloat16(v.w - __bfloat162float(b3));
    __nv_bfloat162* hb2 = (__nv_bfloat162*)hb;
    __nv_bfloat162* hs2 = (__nv_bfloat162*)hs;
    hb2[2*i]   = __nv_bfloat162(b0, b1);
    hb2[2*i+1] = __nv_bfloat162(b2, b3);
    hs2[2*i]   = __nv_bfloat162(s0, s1);
    hs2[2*i+1] = __nv_bfloat162(s2, s3);
}

// ---------------------------------------------------------------------------
// shared helpers
// ---------------------------------------------------------------------------
__device__ __forceinline__ uint32_t sm_u32(const void* p) {
    uint32_t a;
    asm("{ .reg .u64 t; cvta.to.shared.u64 t, %1; cvt.u32.u64 %0, t; }"
        : "=r"(a) : "l"(p));
    return a;
}
__device__ __forceinline__ void cpasync16(uint32_t dst, const void* src) {
    asm volatile("cp.async.cg.shared.global [%0], [%1], 16;"
                 :: "r"(dst), "l"(src));
}
__device__ __forceinline__ void ldsm_x4(uint32_t* r, uint32_t addr) {
    asm volatile("ldmatrix.sync.aligned.m8n8.x4.shared.b16 {%0,%1,%2,%3}, [%4];"
                 : "=r"(r[0]), "=r"(r[1]), "=r"(r[2]), "=r"(r[3]) : "r"(addr));
}
__device__ __forceinline__ void ldsm_x4_t(uint32_t* r, uint32_t addr) {
    asm volatile("ldmatrix.sync.aligned.m8n8.x4.trans.shared.b16 {%0,%1,%2,%3}, [%4];"
                 : "=r"(r[0]), "=r"(r[1]), "=r"(r[2]), "=r"(r[3]) : "r"(addr));
}
__device__ __forceinline__ void mma_bf16(float* d, const uint32_t* a,
                                         const uint32_t* b) {
    asm volatile(
        "mma.sync.aligned.m16n8k16.row.col.f32.bf16.bf16.f32 "
        "{%0,%1,%2,%3}, {%4,%5,%6,%7}, {%8,%9}, {%0,%1,%2,%3};"
        : "+f"(d[0]), "+f"(d[1]), "+f"(d[2]), "+f"(d[3])
        : "r"(a[0]), "r"(a[1]), "r"(a[2]), "r"(a[3]), "r"(b[0]), "r"(b[1]));
}
__device__ __forceinline__ void split_pack(float lo, float hi,
                                           uint32_t& pb, uint32_t& ps) {
    __nv_bfloat16 bl = __float2bfloat16(lo), bh = __float2bfloat16(hi);
    __nv_bfloat162 v(bl, bh);
    pb = *(uint32_t*)&v;
    __nv_bfloat16 sl = __float2bfloat16(lo - __bfloat162float(bl));
    __nv_bfloat16 sh = __float2bfloat16(hi - __bfloat162float(bh));
    __nv_bfloat162 w(sl, sh);
    ps = *(uint32_t*)&w;
}

// ---------------------------------------------------------------------------
// mma.sync bf16x3 GEMM (unchanged, passing): C = A*W^T via Ab*Wb+Ab*Ws+As*Wb
// ---------------------------------------------------------------------------
#define BM 128
#define BN 128
#define BK 64
#define GK 4096
#define GN 4096

#define STAGE  65536
#define OFF_AB 0
#define OFF_AS 16384
#define OFF_BB 32768
#define OFF_BS 49152
#define GEMM_SMEM (2*STAGE)

#define SWZ(x) ((x) ^ (((x) >> 3) & 0x70))

__global__ __launch_bounds__(256, 1)
void gemm_tc(const __nv_bfloat16* __restrict__ Abig,
             const __nv_bfloat16* __restrict__ Asml,
             const __nv_bfloat16* __restrict__ Bbig,
             const __nv_bfloat16* __restrict__ Bsml,
             float* __restrict__ C)
{
    extern __shared__ char smem[];
    const uint32_t sb = sm_u32(smem);
    const int tid = threadIdx.x, wid = tid >> 5, lane = tid & 31;
    const int bm = blockIdx.y * BM, bn = blockIdx.x * BN;
    const int wm = (wid >> 2) * 64;
    const int wn = (wid & 3) * 32;

    const int lr = tid >> 3;
    const int lg = (tid & 7) * 16;

    float acc[4][4][4];
#pragma unroll
    for (int i = 0; i < 4; i++)
#pragma unroll
        for (int j = 0; j < 4; j++)
#pragma unroll
            for (int q = 0; q < 4; q++) acc[i][j][q] = 0.f;

    const int nIter = GK / BK;

    auto load_stage = [&](int s, int c) {
        const int kc = c * BK;
        uint32_t st = sb + s * STAGE;
#pragma unroll
        for (int t = 0; t < 4; t++) {
            int r = lr + t * 32;
            uint32_t so = SWZ((uint32_t)(r * 128) + lg);
            const __nv_bfloat16* ga = Abig + (size_t)(bm + r) * GK + kc;
            const __nv_bfloat16* gs = Asml + (size_t)(bm + r) * GK + kc;
            const __nv_bfloat16* gb = Bbig + (size_t)(bn + r) * GK + kc;
            const __nv_bfloat16* gt = Bsml + (size_t)(bn + r) * GK + kc;
            cpasync16(st + OFF_AB + so, (const char*)ga + lg);
            cpasync16(st + OFF_AS + so, (const char*)gs + lg);
            cpasync16(st + OFF_BB + so, (const char*)gb + lg);
            cpasync16(st + OFF_BS + so, (const char*)gt + lg);
        }
        asm volatile("cp.async.commit_group;");
    };

    load_stage(0, 0);
    load_stage(1, 1);

    const int a_row = (lane & 7) + ((lane >> 3) & 1) * 8;
    const int a_kh  = ((lane >> 4) & 1) * 16;
    const int b_row = (lane & 7) + ((lane >> 4) & 1) * 8;
    const int b_kh  = ((lane >> 3) & 1) * 16;

    for (int c = 0; c < nIter; c++) {
        if (c + 2 < nIter) asm volatile("cp.async.wait_group 1;");
        else               asm volatile("cp.async.wait_group 0;");
        __syncthreads();

        uint32_t st = sb + (c & 1) * STAGE;
#pragma unroll
        for (int ks = 0; ks < 4; ks++) {
            const uint32_t kb = ks * 32;
            uint32_t ab[4][4], as_[4][4], bb[2][4], bs[2][4];
#pragma unroll
            for (int i = 0; i < 4; i++) {
                int row = wm + i * 16 + a_row;
                uint32_t off = SWZ((uint32_t)(row * 128) + kb + a_kh);
                ldsm_x4(ab[i],  st + OFF_AB + off);
                ldsm_x4(as_[i], st + OFF_AS + off);
            }
#pragma unroll
            for (int jp = 0; jp < 2; jp++) {
                int row = wn + jp * 16 + b_row;
                uint32_t off = SWZ((uint32_t)(row * 128) + kb + b_kh);
                ldsm_x4(bb[jp], st + OFF_BB + off);
                ldsm_x4(bs[jp], st + OFF_BS + off);
            }
#pragma unroll
            for (int i = 0; i < 4; i++)
#pragma unroll
                for (int j = 0; j < 4; j++) {
                    const uint32_t* vb = &bb[j >> 1][(j & 1) * 2];
                    const uint32_t* vs = &bs[j >> 1][(j & 1) * 2];
                    mma_bf16(acc[i][j], ab[i],  vb);
                    mma_bf16(acc[i][j], ab[i],  vs);
                    mma_bf16(acc[i][j], as_[i], vb);
                }
        }
        __syncthreads();
        if (c + 2 < nIter) load_stage(c & 1, c + 2);
    }

    const int g  = lane >> 2;
    const int tq = (lane & 3) * 2;
#pragma unroll
    for (int i = 0; i < 4; i++) {
        int row = bm + wm + i * 16 + g;
#pragma unroll
        for (int j = 0; j < 4; j++) {
            int col = bn + wn + j * 8 + tq;
            *(float2*)&C[(size_t)row * GN + col] =
                make_float2(acc[i][j][0], acc[i][j][1]);
            *(float2*)&C[(size_t)(row + 8) * GN + col] =
                make_float2(acc[i][j][2], acc[i][j][3]);
        }
    }
}

// ---------------------------------------------------------------------------
// RoPE + split: reads fp32 Q,K; writes bf16 big/small splits.
// Q is pre-scaled by 1/sqrt(Dh).
// ---------------------------------------------------------------------------
__global__ __launch_bounds__(256)
void rope_split(const float* __restrict__ Q, const float* __restrict__ K,
                __nv_bfloat16* __restrict__ Qb, __nv_bfloat16* __restrict__ Qs,
                __nv_bfloat16* __restrict__ Kb, __nv_bfloat16* __restrict__ Ks)
{
    int idx = blockIdx.x * blockDim.x + threadIdx.x;
    int n = idx >> 6;
    int j = idx & 63;
    int t = (n >> 5) & (TT - 1);
    int m = (j < 32) ? 2 * j : 2 * j - 64;
    float freq = __expf(-(float)m * (9.903487552536127f / 64.0f));
    float s, c;
    sincosf((float)t * freq, &s, &c);
    size_t base = (size_t)n * 128 + 2 * j;
    float2 q = *(float2*)&Q[base];
    float2 k = *(float2*)&K[base];
    const float scale = 0.08838834764831845f;
    float q1 = (q.x * c - q.y * s) * scale, q2 = (q.x * s + q.y * c) * scale;
    float k1 =  k.x * c - k.y * s,          k2 =  k.x * s + k.y * c;

    __nv_bfloat16 qb1 = __float2bfloat16(q1), qb2 = __float2bfloat16(q2);
    __nv_bfloat16 kb1 = __float2bfloat16(k1), kb2 = __float2bfloat16(k2);
    *(__nv_bfloat162*)(Qb + base) = __nv_bfloat162(qb1, qb2);
    *(__nv_bfloat162*)(Kb + base) = __nv_bfloat162(kb1, kb2);
    *(__nv_bfloat162*)(Qs + base) = __nv_bfloat162(
        __float2bfloat16(q1 - __bfloat162float(qb1)),
        __float2bfloat16(q2 - __bfloat162float(qb2)));
    *(__nv_bfloat162*)(Ks + base) = __nv_bfloat162(
        __float2bfloat16(k1 - __bfloat162float(kb1)),
        __float2bfloat16(k2 - __bfloat162float(kb2)));
}

// ---------------------------------------------------------------------------
// Tensor-core flash attention (causal), bf16x3, 2-stage K/V pipeline.
// CTA: (b,h,q-tile of 128 rows), 256 thr (8 warps x 16 q-rows), k-tile 64.
// SMEM: Q 64KB | KV stage0 64KB | KV stage1 64KB = 192KB.
// ---------------------------------------------------------------------------
#define AOFF_QB 0
#define AOFF_QS 32768
#define AOFF_KV 65536          // + s*65536 ; within: KB 0 | KS 16K | VB 32K | VS 48K
#define KV_KB 0
#define KV_KS 16384
#define KV_VB 32768
#define KV_VS 49152
#define ATT_SMEM 196608

#define SWZ256(r, c16) ((uint32_t)((r) * 256 + (((c16) ^ ((r) & 7)) << 4)))

__global__ __launch_bounds__(256, 1)
void attn_tc(const __nv_bfloat16* __restrict__ Qb, const __nv_bfloat16* __restrict__ Qs,
             const __nv_bfloat16* __restrict__ Kb, const __nv_bfloat16* __restrict__ Ks,
             const __nv_bfloat16* __restrict__ Vb, const __nv_bfloat16* __restrict__ Vs,
             float* __restrict__ O)
{
    extern __shared__ char smem[];
    const uint32_t sb = sm_u32(smem);
    const int tid = threadIdx.x, wid = tid >> 5, lane = tid & 31;
    const int qt = blockIdx.x;            // q tile (16)
    const int bh = blockIdx.y;            // b*32+h (64)
    const int b  = bh >> 5, h = bh & 31;
    const size_t head = (size_t)b * TT * TD + (size_t)h * DH;
    const int wm = wid * 16;              // warp q-row offset in tile

    // ---- Q tile (128 rows x 128 d) big+small : commit group 0 ----
#pragma unroll
    for (int i = 0; i < 8; i++) {
        int g = tid + i * 256;
        int r = g >> 4, c = g & 15;
        const char* src = (const char*)(Qb + head + (size_t)(qt * 128 + r) * TD) + c * 16;
        const char* srs = (const char*)(Qs + head + (size_t)(qt * 128 + r) * TD) + c * 16;
        cpasync16(sb + AOFF_QB + SWZ256(r, c), src);
        cpasync16(sb + AOFF_QS + SWZ256(r, c), srs);
    }
    asm volatile("cp.async.commit_group;");

    auto load_kv = [&](int s, int kt) {
        uint32_t base = sb + AOFF_KV + (uint32_t)s * 65536u;
#pragma unroll
        for (int i = 0; i < 4; i++) {
            int g = tid + i * 256;
            int r = g >> 4, c = g & 15;
            size_t grow = head + (size_t)(kt * 64 + r) * TD;
            uint32_t so = SWZ256(r, c);
            cpasync16(base + KV_KB + so, (const char*)(Kb + grow) + c * 16);
            cpasync16(base + KV_KS + so, (const char*)(Ks + grow) + c * 16);
            cpasync16(base + KV_VB + so, (const char*)(Vb + grow) + c * 16);
            cpasync16(base + KV_VS + so, (const char*)(Vs + grow) + c * 16);
        }
        asm volatile("cp.async.commit_group;");
    };

    // lane fragment addressing (proven mapping)
    const int a_row = (lane & 7) + ((lane >> 3) & 1) * 8;
    const int a_k16 = (lane >> 4) & 1;
    const int b_row = (lane & 7) + ((lane >> 4) & 1) * 8;
    const int b_k16 = (lane >> 3) & 1;
    const int v_row = (lane & 7) + ((lane >> 3) & 1) * 8;
    const int v_c16 = (lane >> 4) & 1;

    float oacc[16][4];
#pragma unroll
    for (int nt = 0; nt < 16; nt++)
#pragma unroll
        for (int q = 0; q < 4; q++) oacc[nt][q] = 0.f;
    float mrow[2] = {-1e30f, -1e30f};
    float lsum[2] = {0.f, 0.f};

    const int q_lo = qt * 128 + wm + (lane >> 2);   // global q of row-half 0

    const int nkt = 2 * qt + 2;
    load_kv(0, 0);                                  // prefetch first KV tile

    for (int kt = 0; kt < nkt; kt++) {
        const int st = kt & 1;
        if (kt + 1 < nkt) {
            load_kv(st ^ 1, kt + 1);                // prefetch next tile
            asm volatile("cp.async.wait_group 1;"); // stage kt (and Q) ready
        } else {
            asm volatile("cp.async.wait_group 0;");
        }
        __syncthreads();

        const uint32_t kvb = sb + AOFF_KV + (uint32_t)st * 65536u;

        // ---- S = Q K^T (bf16x3), S tiles st=0..7 cover 64 keys ----
        float sacc[8][4];
#pragma unroll
        for (int s8 = 0; s8 < 8; s8++)
#pragma unroll
            for (int q = 0; q < 4; q++) sacc[s8][q] = 0.f;

#pragma unroll
        for (int dc = 0; dc < 8; dc++) {
            uint32_t qb_[4], qs_[4];
            uint32_t qoff = SWZ256(wm + a_row, dc * 2 + a_k16);
            ldsm_x4(qb_, sb + AOFF_QB + qoff);
            ldsm_x4(qs_, sb + AOFF_QS + qoff);
#pragma unroll
            for (int ntp = 0; ntp < 4; ntp++) {
                uint32_t kb_[4], ks_[4];
                uint32_t koff = SWZ256(ntp * 16 + b_row, dc * 2 + b_k16);
                ldsm_x4(kb_, kvb + KV_KB + koff);
                ldsm_x4(ks_, kvb + KV_KS + koff);
#pragma unroll
                for (int j = 0; j < 2; j++) {
                    float* d = sacc[ntp * 2 + j];
                    mma_bf16(d, qb_, &kb_[2 * j]);
                    mma_bf16(d, qb_, &ks_[2 * j]);
                    mma_bf16(d, qs_, &kb_[2 * j]);
                }
            }
        }

        // ---- causal mask (only diagonal-adjacent k-tiles need it) ----
        if (kt >= 2 * qt) {
#pragma unroll
            for (int s8 = 0; s8 < 8; s8++) {
                int key0 = kt * 64 + s8 * 8 + 2 * (lane & 3);
#pragma unroll
                for (int e = 0; e < 2; e++) {
                    if (key0 + e > q_lo)     sacc[s8][e]     = -1e30f;
                    if (key0 + e > q_lo + 8) sacc[s8][2 + e] = -1e30f;
                }
            }
        }

        // ---- online softmax (rows q_lo, q_lo+8 per lane) ----
        float alpha[2];
#pragma unroll
        for (int hh = 0; hh < 2; hh++) {
            float mx = -1e30f;
#pragma unroll
            for (int s8 = 0; s8 < 8; s8++)
                mx = fmaxf(mx, fmaxf(sacc[s8][2 * hh], sacc[s8][2 * hh + 1]));
            mx = fmaxf(mx, __shfl_xor_sync(0xffffffffu, mx, 1));
            mx = fmaxf(mx, __shfl_xor_sync(0xffffffffu, mx, 2));
            float mn = fmaxf(mrow[hh], mx);
            alpha[hh] = __expf(mrow[hh] - mn);
            mrow[hh] = mn;
            float rs = 0.f;
#pragma unroll
            for (int s8 = 0; s8 < 8; s8++) {
                float p0 = __expf(sacc[s8][2 * hh]     - mn);
                float p1 = __expf(sacc[s8][2 * hh + 1] - mn);
                sacc[s8][2 * hh] = p0; sacc[s8][2 * hh + 1] = p1;
                rs += p0 + p1;
            }
            rs += __shfl_xor_sync(0xffffffffu, rs, 1);
            rs += __shfl_xor_sync(0xffffffffu, rs, 2);
            lsum[hh] = lsum[hh] * alpha[hh] + rs;
        }
#pragma unroll
        for (int nt = 0; nt < 16; nt++) {
            oacc[nt][0] *= alpha[0]; oacc[nt][1] *= alpha[0];
            oacc[nt][2] *= alpha[1]; oacc[nt][3] *= alpha[1];
        }

        // ---- O += P V (bf16x3); P frags straight from S accumulators ----
#pragma unroll
        for (int kc = 0; kc < 4; kc++) {
            uint32_t pb[4], ps[4];
            split_pack(sacc[2*kc][0],   sacc[2*kc][1],   pb[0], ps[0]);
            split_pack(sacc[2*kc][2],   sacc[2*kc][3],   pb[1], ps[1]);
            split_pack(sacc[2*kc+1][0], sacc[2*kc+1][1], pb[2], ps[2]);
            split_pack(sacc[2*kc+1][2], sacc[2*kc+1][3], pb[3], ps[3]);
#pragma unroll
            for (int np = 0; np < 8; np++) {
                uint32_t vb_[4], vs_[4];
                uint32_t voff = SWZ256(kc * 16 + v_row, np * 2 + v_c16);
                ldsm_x4_t(vb_, kvb + KV_VB + voff);
                ldsm_x4_t(vs_, kvb + KV_VS + voff);
#pragma unroll
                for (int j = 0; j < 2; j++) {
                    float* d = oacc[np * 2 + j];
                    mma_bf16(d, pb, &vb_[2 * j]);
                    mma_bf16(d, pb, &vs_[2 * j]);
                    mma_bf16(d, ps, &vb_[2 * j]);
                }
            }
        }
        __syncthreads();   // all reads of stage st done before it's overwritten
    }

    // ---- epilogue: O /= l, write [b,t][h*128+d] ----
    float inv0 = 1.0f / lsum[0], inv1 = 1.0f / lsum[1];
    int row0 = b * TT + q_lo;
#pragma unroll
    for (int nt = 0; nt < 16; nt++) {
        int col = h * DH + nt * 8 + 2 * (lane & 3);
        *(float2*)&O[(size_t)row0 * TD + col] =
            make_float2(oacc[nt][0] * inv0, oacc[nt][1] * inv0);
        *(float2*)&O[(size_t)(row0 + 8) * TD + col] =
            make_float2(oacc[nt][2] * inv1, oacc[nt][3] * inv1);
    }
}

// ---------------------------------------------------------------------------
extern "C" void kernel_launch(void* const* d_in, const int* in_sizes, int n_in,
                              void* d_out, int out_size)
{
    const float* X  = (const float*)d_in[0];
    const float* Wq = (const float*)d_in[1];
    const float* Wk = (const float*)d_in[2];
    const float* Wv = (const float*)d_in[3];
    const float* Wo = (const float*)d_in[4];
    float* out = (float*)d_out;

    float *Qp, *Kp, *Vp, *Ap;
    cudaGetSymbolAddress((void**)&Qp, g_Q);
    cudaGetSymbolAddress((void**)&Kp, g_K);
    cudaGetSymbolAddress((void**)&Vp, g_V);
    cudaGetSymbolAddress((void**)&Ap, g_A);
    __nv_bfloat16 *Xb, *Xs, *Wqb, *Wqs, *Wkb, *Wks, *Wvb, *Wvs, *Wob, *Wos, *Ab, *As;
    cudaGetSymbolAddress((void**)&Xb,  g_Xb);  cudaGetSymbolAddress((void**)&Xs,  g_Xs);
    cudaGetSymbolAddress((void**)&Wqb, g_Wqb); cudaGetSymbolAddress((void**)&Wqs, g_Wqs);
    cudaGetSymbolAddress((void**)&Wkb, g_Wkb); cudaGetSymbolAddress((void**)&Wks, g_Wks);
    cudaGetSymbolAddress((void**)&Wvb, g_Wvb); cudaGetSymbolAddress((void**)&Wvs, g_Wvs);
    cudaGetSymbolAddress((void**)&Wob, g_Wob); cudaGetSymbolAddress((void**)&Wos, g_Wos);
    cudaGetSymbolAddress((void**)&Ab,  g_Ab);  cudaGetSymbolAddress((void**)&As,  g_As);

    cudaFuncSetAttribute(gemm_tc, cudaFuncAttributeMaxDynamicSharedMemorySize,
                         GEMM_SMEM);
    cudaFuncSetAttribute(attn_tc, cudaFuncAttributeMaxDynamicSharedMemorySize,
                         ATT_SMEM);

    const int n4 = (int)((size_t)TD * TD / 4);
    split_bf16<<<n4 / 256, 256>>>(X,  Xb,  Xs);
    split_bf16<<<n4 / 256, 256>>>(Wq, Wqb, Wqs);
    split_bf16<<<n4 / 256, 256>>>(Wk, Wkb, Wks);
    split_bf16<<<n4 / 256, 256>>>(Wv, Wvb, Wvs);
    split_bf16<<<n4 / 256, 256>>>(Wo, Wob, Wos);

    dim3 gg(GN / BN, NTOK / BM);
    gemm_tc<<<gg, 256, GEMM_SMEM>>>(Xb, Xs, Wqb, Wqs, Qp);
    gemm_tc<<<gg, 256, GEMM_SMEM>>>(Xb, Xs, Wkb, Wks, Kp);
    gemm_tc<<<gg, 256, GEMM_SMEM>>>(Xb, Xs, Wvb, Wvs, Vp);

    // Wq/Wk/Wv splits are dead now -> reuse as Q/K/V bf16 split buffers
    const int npairs = TB * TT * TH * 64;
    rope_split<<<npairs / 256, 256>>>(Qp, Kp, Wqb, Wqs, Wkb, Wks);
    split_bf16<<<n4 / 256, 256>>>(Vp, Wvb, Wvs);

    attn_tc<<<dim3(TT / 128, TB * TH), 256, ATT_SMEM>>>(
        Wqb, Wqs, Wkb, Wks, Wvb, Wvs, Ap);

    split_bf16<<<n4 / 256, 256>>>(Ap, Ab, As);
    gemm_tc<<<gg, 256, GEMM_SMEM>>>(Ab, As, Wob, Wos, out);
}

// round 14
// speedup vs baseline: 4.6639x; 1.3089x over previous
#include <cuda_runtime.h>
#include <cuda_bf16.h>
#include <cuda_fp16.h>
#include <cstdint>

#define TB 2
#define TT 2048
#define TD 4096
#define TH 32
#define DH 128
#define NTOK (TB*TT)

// ---------------- scratch (device globals: allocation-free rule) ------------
__device__ float g_Q[(size_t)NTOK*TD];
__device__ float g_K[(size_t)NTOK*TD];
__device__ float g_V[(size_t)NTOK*TD];
__device__ float g_A[(size_t)NTOK*TD];

// fp16 GEMM operands
__device__ __half g_hXb[(size_t)NTOK*TD], g_hXs[(size_t)NTOK*TD];
__device__ __half g_hWq[(size_t)TD*TD], g_hWk[(size_t)TD*TD];
__device__ __half g_hWv[(size_t)TD*TD], g_hWo[(size_t)TD*TD];
__device__ __half g_hAb[(size_t)NTOK*TD], g_hAs[(size_t)NTOK*TD];

// bf16 attention operands (Q/K/V big+small splits)
__device__ __nv_bfloat16 g_Qb[(size_t)NTOK*TD], g_Qs[(size_t)NTOK*TD];
__device__ __nv_bfloat16 g_Kb[(size_t)NTOK*TD], g_Ks[(size_t)NTOK*TD];
__device__ __nv_bfloat16 g_Vb[(size_t)NTOK*TD], g_Vs[(size_t)NTOK*TD];

// ---------------------------------------------------------------------------
// fp32 -> fp16 (big, small) split
// ---------------------------------------------------------------------------
__global__ __launch_bounds__(256)
void split_fp16(const float* __restrict__ x, __half* __restrict__ hb,
                __half* __restrict__ hs)
{
    int i = blockIdx.x * blockDim.x + threadIdx.x;
    float4 v = ((const float4*)x)[i];
    __half b0 = __float2half_rn(v.x), b1 = __float2half_rn(v.y);
    __half b2 = __float2half_rn(v.z), b3 = __float2half_rn(v.w);
    __half s0 = __float2half_rn(v.x - __half2float(b0));
    __half s1 = __float2half_rn(v.y - __half2float(b1));
    __half s2 = __float2half_rn(v.z - __half2float(b2));
    __half s3 = __float2half_rn(v.w - __half2float(b3));
    __half2* hb2 = (__half2*)hb;
    __half2* hs2 = (__half2*)hs;
    hb2[2*i]   = __half2(b0, b1);
    hb2[2*i+1] = __half2(b2, b3);
    hs2[2*i]   = __half2(s0, s1);
    hs2[2*i+1] = __half2(s2, s3);
}

// fp32 -> fp16 single (weights)
__global__ __launch_bounds__(256)
void conv_fp16(const float* __restrict__ x, __half* __restrict__ h)
{
    int i = blockIdx.x * blockDim.x + threadIdx.x;
    float4 v = ((const float4*)x)[i];
    __half2* h2 = (__half2*)h;
    h2[2*i]   = __floats2half2_rn(v.x, v.y);
    h2[2*i+1] = __floats2half2_rn(v.z, v.w);
}

// fp32 -> bf16 (big, small) split (for V in attention)
__global__ __launch_bounds__(256)
void split_bf16(const float* __restrict__ x, __nv_bfloat16* __restrict__ hb,
                __nv_bfloat16* __restrict__ hs)
{
    int i = blockIdx.x * blockDim.x + threadIdx.x;
    float4 v = ((const float4*)x)[i];
    __nv_bfloat16 b0 = __float2bfloat16(v.x);
    __nv_bfloat16 b1 = __float2bfloat16(v.y);
    __nv_bfloat16 b2 = __float2bfloat16(v.z);
    __nv_bfloat16 b3 = __float2bfloat16(v.w);
    __nv_bfloat16 s0 = __float2bfloat16(v.x - __bfloat162float(b0));
    __nv_bfloat16 s1 = __float2bfloat16(v.y - __bfloat162float(b1));
    __nv_bfloat16 s2 = __float2bfloat16(v.z - __bfloat162float(b2));
    __nv_bfloat16 s3 = __float2bfloat16(v.w - __bfloat162float(b3));
    __nv_bfloat162* hb2 = (__nv_bfloat162*)hb;
    __nv_bfloat162* hs2 = (__nv_bfloat162*)hs;
    hb2[2*i]   = __nv_bfloat162(b0, b1);
    hb2[2*i+1] = __nv_bfloat162(b2, b3);
    hs2[2*i]   = __nv_bfloat162(s0, s1);
    hs2[2*i+1] = __nv_bfloat162(s2, s3);
}

// ---------------------------------------------------------------------------
// shared helpers
// ---------------------------------------------------------------------------
__device__ __forceinline__ uint32_t sm_u32(const void* p) {
    uint32_t a;
    asm("{ .reg .u64 t; cvta.to.shared.u64 t, %1; cvt.u32.u64 %0, t; }"
        : "=r"(a) : "l"(p));
    return a;
}
__device__ __forceinline__ void cpasync16(uint32_t dst, const void* src) {
    asm volatile("cp.async.cg.shared.global [%0], [%1], 16;"
                 :: "r"(dst), "l"(src));
}
__device__ __forceinline__ void ldsm_x4(uint32_t* r, uint32_t addr) {
    asm volatile("ldmatrix.sync.aligned.m8n8.x4.shared.b16 {%0,%1,%2,%3}, [%4];"
                 : "=r"(r[0]), "=r"(r[1]), "=r"(r[2]), "=r"(r[3]) : "r"(addr));
}
__device__ __forceinline__ void ldsm_x4_t(uint32_t* r, uint32_t addr) {
    asm volatile("ldmatrix.sync.aligned.m8n8.x4.trans.shared.b16 {%0,%1,%2,%3}, [%4];"
                 : "=r"(r[0]), "=r"(r[1]), "=r"(r[2]), "=r"(r[3]) : "r"(addr));
}
__device__ __forceinline__ void mma_bf16(float* d, const uint32_t* a,
                                         const uint32_t* b) {
    asm volatile(
        "mma.sync.aligned.m16n8k16.row.col.f32.bf16.bf16.f32 "
        "{%0,%1,%2,%3}, {%4,%5,%6,%7}, {%8,%9}, {%0,%1,%2,%3};"
        : "+f"(d[0]), "+f"(d[1]), "+f"(d[2]), "+f"(d[3])
        : "r"(a[0]), "r"(a[1]), "r"(a[2]), "r"(a[3]), "r"(b[0]), "r"(b[1]));
}
__device__ __forceinline__ void mma_f16(float* d, const uint32_t* a,
                                        const uint32_t* b) {
    asm volatile(
        "mma.sync.aligned.m16n8k16.row.col.f32.f16.f16.f32 "
        "{%0,%1,%2,%3}, {%4,%5,%6,%7}, {%8,%9}, {%0,%1,%2,%3};"
        : "+f"(d[0]), "+f"(d[1]), "+f"(d[2]), "+f"(d[3])
        : "r"(a[0]), "r"(a[1]), "r"(a[2]), "r"(a[3]), "r"(b[0]), "r"(b[1]));
}
__device__ __forceinline__ void split_pack(float lo, float hi,
                                           uint32_t& pb, uint32_t& ps) {
    __nv_bfloat16 bl = __float2bfloat16(lo), bh = __float2bfloat16(hi);
    __nv_bfloat162 v(bl, bh);
    pb = *(uint32_t*)&v;
    __nv_bfloat16 sl = __float2bfloat16(lo - __bfloat162float(bl));
    __nv_bfloat16 sh = __float2bfloat16(hi - __bfloat162float(bh));
    __nv_bfloat162 w(sl, sh);
    ps = *(uint32_t*)&w;
}

// ---------------------------------------------------------------------------
// fp16x2 GEMM:  C[m,n] = sum_k A[m,k]*W[n,k];  C = Ab*Wf + As*Wf
// BM=BN=128, BK=64, 256 thr (8 warps 2x4), warp tile 64x32, 2-stage cp.async.
// ---------------------------------------------------------------------------
#define BM 128
#define BN 128
#define BK 64
#define GK 4096
#define GN 4096

#define STAGE  49152
#define OFF_AB 0
#define OFF_AS 16384
#define OFF_BF 32768
#define GEMM_SMEM (2*STAGE)   // 98304

#define SWZ(x) ((x) ^ (((x) >> 3) & 0x70))

__global__ __launch_bounds__(256, 1)
void gemm_f16(const __half* __restrict__ Abig,
              const __half* __restrict__ Asml,
              const __half* __restrict__ Bf,
              float* __restrict__ C)
{
    extern __shared__ char smem[];
    const uint32_t sb = sm_u32(smem);
    const int tid = threadIdx.x, wid = tid >> 5, lane = tid & 31;
    const int bm = blockIdx.y * BM, bn = blockIdx.x * BN;
    const int wm = (wid >> 2) * 64;
    const int wn = (wid & 3) * 32;

    const int lr = tid >> 3;
    const int lg = (tid & 7) * 16;

    float acc[4][4][4];
#pragma unroll
    for (int i = 0; i < 4; i++)
#pragma unroll
        for (int j = 0; j < 4; j++)
#pragma unroll
            for (int q = 0; q < 4; q++) acc[i][j][q] = 0.f;

    const int nIter = GK / BK;

    auto load_stage = [&](int s, int c) {
        const int kc = c * BK;
        uint32_t st = sb + s * STAGE;
#pragma unroll
        for (int t = 0; t < 4; t++) {
            int r = lr + t * 32;
            uint32_t so = SWZ((uint32_t)(r * 128) + lg);
            cpasync16(st + OFF_AB + so,
                      (const char*)(Abig + (size_t)(bm + r) * GK + kc) + lg);
            cpasync16(st + OFF_AS + so,
                      (const char*)(Asml + (size_t)(bm + r) * GK + kc) + lg);
            cpasync16(st + OFF_BF + so,
                      (const char*)(Bf + (size_t)(bn + r) * GK + kc) + lg);
        }
        asm volatile("cp.async.commit_group;");
    };

    load_stage(0, 0);
    load_stage(1, 1);

    const int a_row = (lane & 7) + ((lane >> 3) & 1) * 8;
    const int a_kh  = ((lane >> 4) & 1) * 16;
    const int b_row = (lane & 7) + ((lane >> 4) & 1) * 8;
    const int b_kh  = ((lane >> 3) & 1) * 16;

    for (int c = 0; c < nIter; c++) {
        if (c + 2 < nIter) asm volatile("cp.async.wait_group 1;");
        else               asm volatile("cp.async.wait_group 0;");
        __syncthreads();

        uint32_t st = sb + (c & 1) * STAGE;
#pragma unroll
        for (int ks = 0; ks < 4; ks++) {
            const uint32_t kb = ks * 32;
            uint32_t ab[4][4], as_[4][4], bf[2][4];
#pragma unroll
            for (int i = 0; i < 4; i++) {
                int row = wm + i * 16 + a_row;
                uint32_t off = SWZ((uint32_t)(row * 128) + kb + a_kh);
                ldsm_x4(ab[i],  st + OFF_AB + off);
                ldsm_x4(as_[i], st + OFF_AS + off);
            }
#pragma unroll
            for (int jp = 0; jp < 2; jp++) {
                int row = wn + jp * 16 + b_row;
                uint32_t off = SWZ((uint32_t)(row * 128) + kb + b_kh);
                ldsm_x4(bf[jp], st + OFF_BF + off);
            }
#pragma unroll
            for (int i = 0; i < 4; i++)
#pragma unroll
                for (int j = 0; j < 4; j++) {
                    const uint32_t* vb = &bf[j >> 1][(j & 1) * 2];
                    mma_f16(acc[i][j], ab[i],  vb);
                    mma_f16(acc[i][j], as_[i], vb);
                }
        }
        __syncthreads();
        if (c + 2 < nIter) load_stage(c & 1, c + 2);
    }

    const int g  = lane >> 2;
    const int tq = (lane & 3) * 2;
#pragma unroll
    for (int i = 0; i < 4; i++) {
        int row = bm + wm + i * 16 + g;
#pragma unroll
        for (int j = 0; j < 4; j++) {
            int col = bn + wn + j * 8 + tq;
            *(float2*)&C[(size_t)row * GN + col] =
                make_float2(acc[i][j][0], acc[i][j][1]);
            *(float2*)&C[(size_t)(row + 8) * GN + col] =
                make_float2(acc[i][j][2], acc[i][j][3]);
        }
    }
}

// ---------------------------------------------------------------------------
// RoPE + split (bf16 big/small for attention). Q pre-scaled by 1/sqrt(Dh).
// ---------------------------------------------------------------------------
__global__ __launch_bounds__(256)
void rope_split(const float* __restrict__ Q, const float* __restrict__ K,
                __nv_bfloat16* __restrict__ Qb, __nv_bfloat16* __restrict__ Qs,
                __nv_bfloat16* __restrict__ Kb, __nv_bfloat16* __restrict__ Ks)
{
    int idx = blockIdx.x * blockDim.x + threadIdx.x;
    int n = idx >> 6;
    int j = idx & 63;
    int t = (n >> 5) & (TT - 1);
    int m = (j < 32) ? 2 * j : 2 * j - 64;
    float freq = __expf(-(float)m * (9.903487552536127f / 64.0f));
    float s, c;
    sincosf((float)t * freq, &s, &c);
    size_t base = (size_t)n * 128 + 2 * j;
    float2 q = *(float2*)&Q[base];
    float2 k = *(float2*)&K[base];
    const float scale = 0.08838834764831845f;
    float q1 = (q.x * c - q.y * s) * scale, q2 = (q.x * s + q.y * c) * scale;
    float k1 =  k.x * c - k.y * s,          k2 =  k.x * s + k.y * c;

    __nv_bfloat16 qb1 = __float2bfloat16(q1), qb2 = __float2bfloat16(q2);
    __nv_bfloat16 kb1 = __float2bfloat16(k1), kb2 = __float2bfloat16(k2);
    *(__nv_bfloat162*)(Qb + base) = __nv_bfloat162(qb1, qb2);
    *(__nv_bfloat162*)(Kb + base) = __nv_bfloat162(kb1, kb2);
    *(__nv_bfloat162*)(Qs + base) = __nv_bfloat162(
        __float2bfloat16(q1 - __bfloat162float(qb1)),
        __float2bfloat16(q2 - __bfloat162float(qb2)));
    *(__nv_bfloat162*)(Ks + base) = __nv_bfloat162(
        __float2bfloat16(k1 - __bfloat162float(kb1)),
        __float2bfloat16(k2 - __bfloat162float(kb2)));
}

// ---------------------------------------------------------------------------
// Tensor-core flash attention (causal), bf16x3, 2-stage K/V pipeline.
// (unchanged from passing round)
// ---------------------------------------------------------------------------
#define AOFF_QB 0
#define AOFF_QS 32768
#define AOFF_KV 65536
#define KV_KB 0
#define KV_KS 16384
#define KV_VB 32768
#define KV_VS 49152
#define ATT_SMEM 196608

#define SWZ256(r, c16) ((uint32_t)((r) * 256 + (((c16) ^ ((r) & 7)) << 4)))

__global__ __launch_bounds__(256, 1)
void attn_tc(const __nv_bfloat16* __restrict__ Qb, const __nv_bfloat16* __restrict__ Qs,
             const __nv_bfloat16* __restrict__ Kb, const __nv_bfloat16* __restrict__ Ks,
             const __nv_bfloat16* __restrict__ Vb, const __nv_bfloat16* __restrict__ Vs,
             float* __restrict__ O)
{
    extern __shared__ char smem[];
    const uint32_t sb = sm_u32(smem);
    const int tid = threadIdx.x, wid = tid >> 5, lane = tid & 31;
    const int qt = blockIdx.x;
    const int bh = blockIdx.y;
    const int b  = bh >> 5, h = bh & 31;
    const size_t head = (size_t)b * TT * TD + (size_t)h * DH;
    const int wm = wid * 16;

#pragma unroll
    for (int i = 0; i < 8; i++) {
        int g = tid + i * 256;
        int r = g >> 4, c = g & 15;
        const char* src = (const char*)(Qb + head + (size_t)(qt * 128 + r) * TD) + c * 16;
        const char* srs = (const char*)(Qs + head + (size_t)(qt * 128 + r) * TD) + c * 16;
        cpasync16(sb + AOFF_QB + SWZ256(r, c), src);
        cpasync16(sb + AOFF_QS + SWZ256(r, c), srs);
    }
    asm volatile("cp.async.commit_group;");

    auto load_kv = [&](int s, int kt) {
        uint32_t base = sb + AOFF_KV + (uint32_t)s * 65536u;
#pragma unroll
        for (int i = 0; i < 4; i++) {
            int g = tid + i * 256;
            int r = g >> 4, c = g & 15;
            size_t grow = head + (size_t)(kt * 64 + r) * TD;
            uint32_t so = SWZ256(r, c);
            cpasync16(base + KV_KB + so, (const char*)(Kb + grow) + c * 16);
            cpasync16(base + KV_KS + so, (const char*)(Ks + grow) + c * 16);
            cpasync16(base + KV_VB + so, (const char*)(Vb + grow) + c * 16);
            cpasync16(base + KV_VS + so, (const char*)(Vs + grow) + c * 16);
        }
        asm volatile("cp.async.commit_group;");
    };

    const int a_row = (lane & 7) + ((lane >> 3) & 1) * 8;
    const int a_k16 = (lane >> 4) & 1;
    const int b_row = (lane & 7) + ((lane >> 4) & 1) * 8;
    const int b_k16 = (lane >> 3) & 1;
    const int v_row = (lane & 7) + ((lane >> 3) & 1) * 8;
    const int v_c16 = (lane >> 4) & 1;

    float oacc[16][4];
#pragma unroll
    for (int nt = 0; nt < 16; nt++)
#pragma unroll
        for (int q = 0; q < 4; q++) oacc[nt][q] = 0.f;
    float mrow[2] = {-1e30f, -1e30f};
    float lsum[2] = {0.f, 0.f};

    const int q_lo = qt * 128 + wm + (lane >> 2);

    const int nkt = 2 * qt + 2;
    load_kv(0, 0);

    for (int kt = 0; kt < nkt; kt++) {
        const int st = kt & 1;
        if (kt + 1 < nkt) {
            load_kv(st ^ 1, kt + 1);
            asm volatile("cp.async.wait_group 1;");
        } else {
            asm volatile("cp.async.wait_group 0;");
        }
        __syncthreads();

        const uint32_t kvb = sb + AOFF_KV + (uint32_t)st * 65536u;

        float sacc[8][4];
#pragma unroll
        for (int s8 = 0; s8 < 8; s8++)
#pragma unroll
            for (int q = 0; q < 4; q++) sacc[s8][q] = 0.f;

#pragma unroll
        for (int dc = 0; dc < 8; dc++) {
            uint32_t qb_[4], qs_[4];
            uint32_t qoff = SWZ256(wm + a_row, dc * 2 + a_k16);
            ldsm_x4(qb_, sb + AOFF_QB + qoff);
            ldsm_x4(qs_, sb + AOFF_QS + qoff);
#pragma unroll
            for (int ntp = 0; ntp < 4; ntp++) {
                uint32_t kb_[4], ks_[4];
                uint32_t koff = SWZ256(ntp * 16 + b_row, dc * 2 + b_k16);
                ldsm_x4(kb_, kvb + KV_KB + koff);
                ldsm_x4(ks_, kvb + KV_KS + koff);
#pragma unroll
                for (int j = 0; j < 2; j++) {
                    float* d = sacc[ntp * 2 + j];
                    mma_bf16(d, qb_, &kb_[2 * j]);
                    mma_bf16(d, qb_, &ks_[2 * j]);
                    mma_bf16(d, qs_, &kb_[2 * j]);
                }
            }
        }

        if (kt >= 2 * qt) {
#pragma unroll
            for (int s8 = 0; s8 < 8; s8++) {
                int key0 = kt * 64 + s8 * 8 + 2 * (lane & 3);
#pragma unroll
                for (int e = 0; e < 2; e++) {
                    if (key0 + e > q_lo)     sacc[s8][e]     = -1e30f;
                    if (key0 + e > q_lo + 8) sacc[s8][2 + e] = -1e30f;
                }
            }
        }

        float alpha[2];
#pragma unroll
        for (int hh = 0; hh < 2; hh++) {
            float mx = -1e30f;
#pragma unroll
            for (int s8 = 0; s8 < 8; s8++)
                mx = fmaxf(mx, fmaxf(sacc[s8][2 * hh], sacc[s8][2 * hh + 1]));
            mx = fmaxf(mx, __shfl_xor_sync(0xffffffffu, mx, 1));
            mx = fmaxf(mx, __shfl_xor_sync(0xffffffffu, mx, 2));
            float mn = fmaxf(mrow[hh], mx);
            alpha[hh] = __expf(mrow[hh] - mn);
            mrow[hh] = mn;
            float rs = 0.f;
#pragma unroll
            for (int s8 = 0; s8 < 8; s8++) {
                float p0 = __expf(sacc[s8][2 * hh]     - mn);
                float p1 = __expf(sacc[s8][2 * hh + 1] - mn);
                sacc[s8][2 * hh] = p0; sacc[s8][2 * hh + 1] = p1;
                rs += p0 + p1;
            }
            rs += __shfl_xor_sync(0xffffffffu, rs, 1);
            rs += __shfl_xor_sync(0xffffffffu, rs, 2);
            lsum[hh] = lsum[hh] * alpha[hh] + rs;
        }
#pragma unroll
        for (int nt = 0; nt < 16; nt++) {
            oacc[nt][0] *= alpha[0]; oacc[nt][1] *= alpha[0];
            oacc[nt][2] *= alpha[1]; oacc[nt][3] *= alpha[1];
        }

#pragma unroll
        for (int kc = 0; kc < 4; kc++) {
            uint32_t pb[4], ps[4];
            split_pack(sacc[2*kc][0],   sacc[2*kc][1],   pb[0], ps[0]);
            split_pack(sacc[2*kc][2],   sacc[2*kc][3],   pb[1], ps[1]);
            split_pack(sacc[2*kc+1][0], sacc[2*kc+1][1], pb[2], ps[2]);
            split_pack(sacc[2*kc+1][2], sacc[2*kc+1][3], pb[3], ps[3]);
#pragma unroll
            for (int np = 0; np < 8; np++) {
                uint32_t vb_[4], vs_[4];
                uint32_t voff = SWZ256(kc * 16 + v_row, np * 2 + v_c16);
                ldsm_x4_t(vb_, kvb + KV_VB + voff);
                ldsm_x4_t(vs_, kvb + KV_VS + voff);
#pragma unroll
                for (int j = 0; j < 2; j++) {
                    float* d = oacc[np * 2 + j];
                    mma_bf16(d, pb, &vb_[2 * j]);
                    mma_bf16(d, pb, &vs_[2 * j]);
                    mma_bf16(d, ps, &vb_[2 * j]);
                }
            }
        }
        __syncthreads();
    }

    float inv0 = 1.0f / lsum[0], inv1 = 1.0f / lsum[1];
    int row0 = b * TT + q_lo;
#pragma unroll
    for (int nt = 0; nt < 16; nt++) {
        int col = h * DH + nt * 8 + 2 * (lane & 3);
        *(float2*)&O[(size_t)row0 * TD + col] =
            make_float2(oacc[nt][0] * inv0, oacc[nt][1] * inv0);
        *(float2*)&O[(size_t)(row0 + 8) * TD + col] =
            make_float2(oacc[nt][2] * inv1, oacc[nt][3] * inv1);
    }
}

// ---------------------------------------------------------------------------
extern "C" void kernel_launch(void* const* d_in, const int* in_sizes, int n_in,
                              void* d_out, int out_size)
{
    const float* X  = (const float*)d_in[0];
    const float* Wq = (const float*)d_in[1];
    const float* Wk = (const float*)d_in[2];
    const float* Wv = (const float*)d_in[3];
    const float* Wo = (const float*)d_in[4];
    float* out = (float*)d_out;

    float *Qp, *Kp, *Vp, *Ap;
    cudaGetSymbolAddress((void**)&Qp, g_Q);
    cudaGetSymbolAddress((void**)&Kp, g_K);
    cudaGetSymbolAddress((void**)&Vp, g_V);
    cudaGetSymbolAddress((void**)&Ap, g_A);
    __half *hXb, *hXs, *hWq, *hWk, *hWv, *hWo, *hAb, *hAs;
    cudaGetSymbolAddress((void**)&hXb, g_hXb); cudaGetSymbolAddress((void**)&hXs, g_hXs);
    cudaGetSymbolAddress((void**)&hWq, g_hWq); cudaGetSymbolAddress((void**)&hWk, g_hWk);
    cudaGetSymbolAddress((void**)&hWv, g_hWv); cudaGetSymbolAddress((void**)&hWo, g_hWo);
    cudaGetSymbolAddress((void**)&hAb, g_hAb); cudaGetSymbolAddress((void**)&hAs, g_hAs);
    __nv_bfloat16 *Qb, *Qs, *Kb, *Ks, *Vb, *Vs;
    cudaGetSymbolAddress((void**)&Qb, g_Qb); cudaGetSymbolAddress((void**)&Qs, g_Qs);
    cudaGetSymbolAddress((void**)&Kb, g_Kb); cudaGetSymbolAddress((void**)&Ks, g_Ks);
    cudaGetSymbolAddress((void**)&Vb, g_Vb); cudaGetSymbolAddress((void**)&Vs, g_Vs);

    cudaFuncSetAttribute(gemm_f16, cudaFuncAttributeMaxDynamicSharedMemorySize,
                         GEMM_SMEM);
    cudaFuncSetAttribute(attn_tc, cudaFuncAttributeMaxDynamicSharedMemorySize,
                         ATT_SMEM);

    const int n4w = (int)((size_t)TD * TD / 4);
    const int n4x = (int)((size_t)NTOK * TD / 4);
    split_fp16<<<n4x / 256, 256>>>(X, hXb, hXs);
    conv_fp16<<<n4w / 256, 256>>>(Wq, hWq);
    conv_fp16<<<n4w / 256, 256>>>(Wk, hWk);
    conv_fp16<<<n4w / 256, 256>>>(Wv, hWv);
    conv_fp16<<<n4w / 256, 256>>>(Wo, hWo);

    dim3 gg(GN / BN, NTOK / BM);
    gemm_f16<<<gg, 256, GEMM_SMEM>>>(hXb, hXs, hWq, Qp);
    gemm_f16<<<gg, 256, GEMM_SMEM>>>(hXb, hXs, hWk, Kp);
    gemm_f16<<<gg, 256, GEMM_SMEM>>>(hXb, hXs, hWv, Vp);

    const int npairs = TB * TT * TH * 64;
    rope_split<<<npairs / 256, 256>>>(Qp, Kp, Qb, Qs, Kb, Ks);
    split_bf16<<<n4x / 256, 256>>>(Vp, Vb, Vs);

    attn_tc<<<dim3(TT / 128, TB * TH), 256, ATT_SMEM>>>(
        Qb, Qs, Kb, Ks, Vb, Vs, Ap);

    split_fp16<<<n4x / 256, 256>>>(Ap, hAb, hAs);
    gemm_f16<<<gg, 256, GEMM_SMEM>>>(hAb, hAs, hWo, out);
}

// round 15
// speedup vs baseline: 6.7404x; 1.4452x over previous
#include <cuda_runtime.h>
#include <cuda_bf16.h>
#include <cuda_fp16.h>
#include <cstdint>

#define TB 2
#define TT 2048
#define TD 4096
#define TH 32
#define DH 128
#define NTOK (TB*TT)

// ---------------- scratch (device globals: allocation-free rule) ------------
__device__ float g_Q[(size_t)NTOK*TD];
__device__ float g_K[(size_t)NTOK*TD];
__device__ float g_V[(size_t)NTOK*TD];
__device__ float g_A[(size_t)NTOK*TD];

// fp16 GEMM operands (single precision term each)
__device__ __half g_hX[(size_t)NTOK*TD];
__device__ __half g_hWq[(size_t)TD*TD], g_hWk[(size_t)TD*TD];
__device__ __half g_hWv[(size_t)TD*TD], g_hWo[(size_t)TD*TD];
__device__ __half g_hA[(size_t)NTOK*TD];

// bf16 attention operands (Q/K/V big+small splits)
__device__ __nv_bfloat16 g_Qb[(size_t)NTOK*TD], g_Qs[(size_t)NTOK*TD];
__device__ __nv_bfloat16 g_Kb[(size_t)NTOK*TD], g_Ks[(size_t)NTOK*TD];
__device__ __nv_bfloat16 g_Vb[(size_t)NTOK*TD], g_Vs[(size_t)NTOK*TD];

// ---------------------------------------------------------------------------
// fp32 -> fp16 convert
// ---------------------------------------------------------------------------
__global__ __launch_bounds__(256)
void conv_fp16(const float* __restrict__ x, __half* __restrict__ h)
{
    int i = blockIdx.x * blockDim.x + threadIdx.x;
    float4 v = ((const float4*)x)[i];
    __half2* h2 = (__half2*)h;
    h2[2*i]   = __floats2half2_rn(v.x, v.y);
    h2[2*i+1] = __floats2half2_rn(v.z, v.w);
}

// fp32 -> bf16 (big, small) split (for V in attention)
__global__ __launch_bounds__(256)
void split_bf16(const float* __restrict__ x, __nv_bfloat16* __restrict__ hb,
                __nv_bfloat16* __restrict__ hs)
{
    int i = blockIdx.x * blockDim.x + threadIdx.x;
    float4 v = ((const float4*)x)[i];
    __nv_bfloat16 b0 = __float2bfloat16(v.x);
    __nv_bfloat16 b1 = __float2bfloat16(v.y);
    __nv_bfloat16 b2 = __float2bfloat16(v.z);
    __nv_bfloat16 b3 = __float2bfloat16(v.w);
    __nv_bfloat16 s0 = __float2bfloat16(v.x - __bfloat162float(b0));
    __nv_bfloat16 s1 = __float2bfloat16(v.y - __bfloat162float(b1));
    __nv_bfloat16 s2 = __float2bfloat16(v.z - __bfloat162float(b2));
    __nv_bfloat16 s3 = __float2bfloat16(v.w - __bfloat162float(b3));
    __nv_bfloat162* hb2 = (__nv_bfloat162*)hb;
    __nv_bfloat162* hs2 = (__nv_bfloat162*)hs;
    hb2[2*i]   = __nv_bfloat162(b0, b1);
    hb2[2*i+1] = __nv_bfloat162(b2, b3);
    hs2[2*i]   = __nv_bfloat162(s0, s1);
    hs2[2*i+1] = __nv_bfloat162(s2, s3);
}

// ---------------------------------------------------------------------------
// shared helpers
// ---------------------------------------------------------------------------
__device__ __forceinline__ uint32_t sm_u32(const void* p) {
    uint32_t a;
    asm("{ .reg .u64 t; cvta.to.shared.u64 t, %1; cvt.u32.u64 %0, t; }"
        : "=r"(a) : "l"(p));
    return a;
}
__device__ __forceinline__ void cpasync16(uint32_t dst, const void* src) {
    asm volatile("cp.async.cg.shared.global [%0], [%1], 16;"
                 :: "r"(dst), "l"(src));
}
__device__ __forceinline__ void ldsm_x4(uint32_t* r, uint32_t addr) {
    asm volatile("ldmatrix.sync.aligned.m8n8.x4.shared.b16 {%0,%1,%2,%3}, [%4];"
                 : "=r"(r[0]), "=r"(r[1]), "=r"(r[2]), "=r"(r[3]) : "r"(addr));
}
__device__ __forceinline__ void ldsm_x4_t(uint32_t* r, uint32_t addr) {
    asm volatile("ldmatrix.sync.aligned.m8n8.x4.trans.shared.b16 {%0,%1,%2,%3}, [%4];"
                 : "=r"(r[0]), "=r"(r[1]), "=r"(r[2]), "=r"(r[3]) : "r"(addr));
}
__device__ __forceinline__ void mma_bf16(float* d, const uint32_t* a,
                                         const uint32_t* b) {
    asm volatile(
        "mma.sync.aligned.m16n8k16.row.col.f32.bf16.bf16.f32 "
        "{%0,%1,%2,%3}, {%4,%5,%6,%7}, {%8,%9}, {%0,%1,%2,%3};"
        : "+f"(d[0]), "+f"(d[1]), "+f"(d[2]), "+f"(d[3])
        : "r"(a[0]), "r"(a[1]), "r"(a[2]), "r"(a[3]), "r"(b[0]), "r"(b[1]));
}
__device__ __forceinline__ void mma_f16(float* d, const uint32_t* a,
                                        const uint32_t* b) {
    asm volatile(
        "mma.sync.aligned.m16n8k16.row.col.f32.f16.f16.f32 "
        "{%0,%1,%2,%3}, {%4,%5,%6,%7}, {%8,%9}, {%0,%1,%2,%3};"
        : "+f"(d[0]), "+f"(d[1]), "+f"(d[2]), "+f"(d[3])
        : "r"(a[0]), "r"(a[1]), "r"(a[2]), "r"(a[3]), "r"(b[0]), "r"(b[1]));
}
__device__ __forceinline__ void split_pack(float lo, float hi,
                                           uint32_t& pb, uint32_t& ps) {
    __nv_bfloat16 bl = __float2bfloat16(lo), bh = __float2bfloat16(hi);
    __nv_bfloat162 v(bl, bh);
    pb = *(uint32_t*)&v;
    __nv_bfloat16 sl = __float2bfloat16(lo - __bfloat162float(bl));
    __nv_bfloat16 sh = __float2bfloat16(hi - __bfloat162float(bh));
    __nv_bfloat162 w(sl, sh);
    ps = *(uint32_t*)&w;
}

// ---------------------------------------------------------------------------
// fp16 single-term GEMM:  C[m,n] = sum_k A[m,k]*W[n,k]
// BM=BN=128, BK=64, 256 thr (8 warps 2x4), warp tile 64x32,
// 3-stage cp.async pipeline, one barrier per iteration.
// ---------------------------------------------------------------------------
#define BM 128
#define BN 128
#define BK 64
#define GK 4096
#define GN 4096

#define STAGE  32768
#define OFF_A  0
#define OFF_B  16384
#define GEMM_SMEM (3*STAGE)   // 98304

#define SWZ(x) ((x) ^ (((x) >> 3) & 0x70))

__global__ __launch_bounds__(256, 1)
void gemm_f16(const __half* __restrict__ A,
              const __half* __restrict__ Bf,
              float* __restrict__ C)
{
    extern __shared__ char smem[];
    const uint32_t sb = sm_u32(smem);
    const int tid = threadIdx.x, wid = tid >> 5, lane = tid & 31;
    const int bm = blockIdx.y * BM, bn = blockIdx.x * BN;
    const int wm = (wid >> 2) * 64;
    const int wn = (wid & 3) * 32;

    const int lr = tid >> 3;
    const int lg = (tid & 7) * 16;

    float acc[4][4][4];
#pragma unroll
    for (int i = 0; i < 4; i++)
#pragma unroll
        for (int j = 0; j < 4; j++)
#pragma unroll
            for (int q = 0; q < 4; q++) acc[i][j][q] = 0.f;

    const int nIter = GK / BK;   // 64

    auto load_stage = [&](int s, int c) {
        const int kc = c * BK;
        uint32_t st = sb + s * STAGE;
#pragma unroll
        for (int t = 0; t < 4; t++) {
            int r = lr + t * 32;
            uint32_t so = SWZ((uint32_t)(r * 128) + lg);
            cpasync16(st + OFF_A + so,
                      (const char*)(A + (size_t)(bm + r) * GK + kc) + lg);
            cpasync16(st + OFF_B + so,
                      (const char*)(Bf + (size_t)(bn + r) * GK + kc) + lg);
        }
        asm volatile("cp.async.commit_group;");
    };

    load_stage(0, 0);
    load_stage(1, 1);

    const int a_row = (lane & 7) + ((lane >> 3) & 1) * 8;
    const int a_kh  = ((lane >> 4) & 1) * 16;
    const int b_row = (lane & 7) + ((lane >> 4) & 1) * 8;
    const int b_kh  = ((lane >> 3) & 1) * 16;

    for (int c = 0; c < nIter; c++) {
        if (c + 1 < nIter) asm volatile("cp.async.wait_group 1;");
        else               asm volatile("cp.async.wait_group 0;");
        __syncthreads();
        // prefetch c+2 into the slot last read at iter c-1 (safe: barrier above)
        if (c + 2 < nIter) load_stage((c + 2) % 3, c + 2);

        uint32_t st = sb + (c % 3) * STAGE;
#pragma unroll
        for (int ks = 0; ks < 4; ks++) {
            const uint32_t kb = ks * 32;
            uint32_t af[4][4], bf[2][4];
#pragma unroll
            for (int i = 0; i < 4; i++) {
                int row = wm + i * 16 + a_row;
                ldsm_x4(af[i], st + OFF_A + SWZ((uint32_t)(row * 128) + kb + a_kh));
            }
#pragma unroll
            for (int jp = 0; jp < 2; jp++) {
                int row = wn + jp * 16 + b_row;
                ldsm_x4(bf[jp], st + OFF_B + SWZ((uint32_t)(row * 128) + kb + b_kh));
            }
#pragma unroll
            for (int i = 0; i < 4; i++)
#pragma unroll
                for (int j = 0; j < 4; j++)
                    mma_f16(acc[i][j], af[i], &bf[j >> 1][(j & 1) * 2]);
        }
    }

    const int g  = lane >> 2;
    const int tq = (lane & 3) * 2;
#pragma unroll
    for (int i = 0; i < 4; i++) {
        int row = bm + wm + i * 16 + g;
#pragma unroll
        for (int j = 0; j < 4; j++) {
            int col = bn + wn + j * 8 + tq;
            *(float2*)&C[(size_t)row * GN + col] =
                make_float2(acc[i][j][0], acc[i][j][1]);
            *(float2*)&C[(size_t)(row + 8) * GN + col] =
                make_float2(acc[i][j][2], acc[i][j][3]);
        }
    }
}

// ---------------------------------------------------------------------------
// RoPE + split (bf16 big/small for attention). Q pre-scaled by 1/sqrt(Dh).
// ---------------------------------------------------------------------------
__global__ __launch_bounds__(256)
void rope_split(const float* __restrict__ Q, const float* __restrict__ K,
                __nv_bfloat16* __restrict__ Qb, __nv_bfloat16* __restrict__ Qs,
                __nv_bfloat16* __restrict__ Kb, __nv_bfloat16* __restrict__ Ks)
{
    int idx = blockIdx.x * blockDim.x + threadIdx.x;
    int n = idx >> 6;
    int j = idx & 63;
    int t = (n >> 5) & (TT - 1);
    int m = (j < 32) ? 2 * j : 2 * j - 64;
    float freq = __expf(-(float)m * (9.903487552536127f / 64.0f));
    float s, c;
    sincosf((float)t * freq, &s, &c);
    size_t base = (size_t)n * 128 + 2 * j;
    float2 q = *(float2*)&Q[base];
    float2 k = *(float2*)&K[base];
    const float scale = 0.08838834764831845f;
    float q1 = (q.x * c - q.y * s) * scale, q2 = (q.x * s + q.y * c) * scale;
    float k1 =  k.x * c - k.y * s,          k2 =  k.x * s + k.y * c;

    __nv_bfloat16 qb1 = __float2bfloat16(q1), qb2 = __float2bfloat16(q2);
    __nv_bfloat16 kb1 = __float2bfloat16(k1), kb2 = __float2bfloat16(k2);
    *(__nv_bfloat162*)(Qb + base) = __nv_bfloat162(qb1, qb2);
    *(__nv_bfloat162*)(Kb + base) = __nv_bfloat162(kb1, kb2);
    *(__nv_bfloat162*)(Qs + base) = __nv_bfloat162(
        __float2bfloat16(q1 - __bfloat162float(qb1)),
        __float2bfloat16(q2 - __bfloat162float(qb2)));
    *(__nv_bfloat162*)(Ks + base) = __nv_bfloat162(
        __float2bfloat16(k1 - __bfloat162float(kb1)),
        __float2bfloat16(k2 - __bfloat162float(kb2)));
}

// ---------------------------------------------------------------------------
// Tensor-core flash attention (causal), bf16x3, 2-stage K/V pipeline.
// (unchanged, passing)
// ---------------------------------------------------------------------------
#define AOFF_QB 0
#define AOFF_QS 32768
#define AOFF_KV 65536
#define KV_KB 0
#define KV_KS 16384
#define KV_VB 32768
#define KV_VS 49152
#define ATT_SMEM 196608

#define SWZ256(r, c16) ((uint32_t)((r) * 256 + (((c16) ^ ((r) & 7)) << 4)))

__global__ __launch_bounds__(256, 1)
void attn_tc(const __nv_bfloat16* __restrict__ Qb, const __nv_bfloat16* __restrict__ Qs,
             const __nv_bfloat16* __restrict__ Kb, const __nv_bfloat16* __restrict__ Ks,
             const __nv_bfloat16* __restrict__ Vb, const __nv_bfloat16* __restrict__ Vs,
             float* __restrict__ O)
{
    extern __shared__ char smem[];
    const uint32_t sb = sm_u32(smem);
    const int tid = threadIdx.x, wid = tid >> 5, lane = tid & 31;
    const int qt = blockIdx.x;
    const int bh = blockIdx.y;
    const int b  = bh >> 5, h = bh & 31;
    const size_t head = (size_t)b * TT * TD + (size_t)h * DH;
    const int wm = wid * 16;

#pragma unroll
    for (int i = 0; i < 8; i++) {
        int g = tid + i * 256;
        int r = g >> 4, c = g & 15;
        const char* src = (const char*)(Qb + head + (size_t)(qt * 128 + r) * TD) + c * 16;
        const char* srs = (const char*)(Qs + head + (size_t)(qt * 128 + r) * TD) + c * 16;
        cpasync16(sb + AOFF_QB + SWZ256(r, c), src);
        cpasync16(sb + AOFF_QS + SWZ256(r, c), srs);
    }
    asm volatile("cp.async.commit_group;");

    auto load_kv = [&](int s, int kt) {
        uint32_t base = sb + AOFF_KV + (uint32_t)s * 65536u;
#pragma unroll
        for (int i = 0; i < 4; i++) {
            int g = tid + i * 256;
            int r = g >> 4, c = g & 15;
            size_t grow = head + (size_t)(kt * 64 + r) * TD;
            uint32_t so = SWZ256(r, c);
            cpasync16(base + KV_KB + so, (const char*)(Kb + grow) + c * 16);
            cpasync16(base + KV_KS + so, (const char*)(Ks + grow) + c * 16);
            cpasync16(base + KV_VB + so, (const char*)(Vb + grow) + c * 16);
            cpasync16(base + KV_VS + so, (const char*)(Vs + grow) + c * 16);
        }
        asm volatile("cp.async.commit_group;");
    };

    const int a_row = (lane & 7) + ((lane >> 3) & 1) * 8;
    const int a_k16 = (lane >> 4) & 1;
    const int b_row = (lane & 7) + ((lane >> 4) & 1) * 8;
    const int b_k16 = (lane >> 3) & 1;
    const int v_row = (lane & 7) + ((lane >> 3) & 1) * 8;
    const int v_c16 = (lane >> 4) & 1;

    float oacc[16][4];
#pragma unroll
    for (int nt = 0; nt < 16; nt++)
#pragma unroll
        for (int q = 0; q < 4; q++) oacc[nt][q] = 0.f;
    float mrow[2] = {-1e30f, -1e30f};
    float lsum[2] = {0.f, 0.f};

    const int q_lo = qt * 128 + wm + (lane >> 2);

    const int nkt = 2 * qt + 2;
    load_kv(0, 0);

    for (int kt = 0; kt < nkt; kt++) {
        const int st = kt & 1;
        if (kt + 1 < nkt) {
            load_kv(st ^ 1, kt + 1);
            asm volatile("cp.async.wait_group 1;");
        } else {
            asm volatile("cp.async.wait_group 0;");
        }
        __syncthreads();

        const uint32_t kvb = sb + AOFF_KV + (uint32_t)st * 65536u;

        float sacc[8][4];
#pragma unroll
        for (int s8 = 0; s8 < 8; s8++)
#pragma unroll
            for (int q = 0; q < 4; q++) sacc[s8][q] = 0.f;

#pragma unroll
        for (int dc = 0; dc < 8; dc++) {
            uint32_t qb_[4], qs_[4];
            uint32_t qoff = SWZ256(wm + a_row, dc * 2 + a_k16);
            ldsm_x4(qb_, sb + AOFF_QB + qoff);
            ldsm_x4(qs_, sb + AOFF_QS + qoff);
#pragma unroll
            for (int ntp = 0; ntp < 4; ntp++) {
                uint32_t kb_[4], ks_[4];
                uint32_t koff = SWZ256(ntp * 16 + b_row, dc * 2 + b_k16);
                ldsm_x4(kb_, kvb + KV_KB + koff);
                ldsm_x4(ks_, kvb + KV_KS + koff);
#pragma unroll
                for (int j = 0; j < 2; j++) {
                    float* d = sacc[ntp * 2 + j];
                    mma_bf16(d, qb_, &kb_[2 * j]);
                    mma_bf16(d, qb_, &ks_[2 * j]);
                    mma_bf16(d, qs_, &kb_[2 * j]);
                }
            }
        }

        if (kt >= 2 * qt) {
#pragma unroll
            for (int s8 = 0; s8 < 8; s8++) {
                int key0 = kt * 64 + s8 * 8 + 2 * (lane & 3);
#pragma unroll
                for (int e = 0; e < 2; e++) {
                    if (key0 + e > q_lo)     sacc[s8][e]     = -1e30f;
                    if (key0 + e > q_lo + 8) sacc[s8][2 + e] = -1e30f;
                }
            }
        }

        float alpha[2];
#pragma unroll
        for (int hh = 0; hh < 2; hh++) {
            float mx = -1e30f;
#pragma unroll
            for (int s8 = 0; s8 < 8; s8++)
                mx = fmaxf(mx, fmaxf(sacc[s8][2 * hh], sacc[s8][2 * hh + 1]));
            mx = fmaxf(mx, __shfl_xor_sync(0xffffffffu, mx, 1));
            mx = fmaxf(mx, __shfl_xor_sync(0xffffffffu, mx, 2));
            float mn = fmaxf(mrow[hh], mx);
            alpha[hh] = __expf(mrow[hh] - mn);
            mrow[hh] = mn;
            float rs = 0.f;
#pragma unroll
            for (int s8 = 0; s8 < 8; s8++) {
                float p0 = __expf(sacc[s8][2 * hh]     - mn);
                float p1 = __expf(sacc[s8][2 * hh + 1] - mn);
                sacc[s8][2 * hh] = p0; sacc[s8][2 * hh + 1] = p1;
                rs += p0 + p1;
            }
            rs += __shfl_xor_sync(0xffffffffu, rs, 1);
            rs += __shfl_xor_sync(0xffffffffu, rs, 2);
            lsum[hh] = lsum[hh] * alpha[hh] + rs;
        }
#pragma unroll
        for (int nt = 0; nt < 16; nt++) {
            oacc[nt][0] *= alpha[0]; oacc[nt][1] *= alpha[0];
            oacc[nt][2] *= alpha[1]; oacc[nt][3] *= alpha[1];
        }

#pragma unroll
        for (int kc = 0; kc < 4; kc++) {
            uint32_t pb[4], ps[4];
            split_pack(sacc[2*kc][0],   sacc[2*kc][1],   pb[0], ps[0]);
            split_pack(sacc[2*kc][2],   sacc[2*kc][3],   pb[1], ps[1]);
            split_pack(sacc[2*kc+1][0], sacc[2*kc+1][1], pb[2], ps[2]);
            split_pack(sacc[2*kc+1][2], sacc[2*kc+1][3], pb[3], ps[3]);
#pragma unroll
            for (int np = 0; np < 8; np++) {
                uint32_t vb_[4], vs_[4];
                uint32_t voff = SWZ256(kc * 16 + v_row, np * 2 + v_c16);
                ldsm_x4_t(vb_, kvb + KV_VB + voff);
                ldsm_x4_t(vs_, kvb + KV_VS + voff);
#pragma unroll
                for (int j = 0; j < 2; j++) {
                    float* d = oacc[np * 2 + j];
                    mma_bf16(d, pb, &vb_[2 * j]);
                    mma_bf16(d, pb, &vs_[2 * j]);
                    mma_bf16(d, ps, &vb_[2 * j]);
                }
            }
        }
        __syncthreads();
    }

    float inv0 = 1.0f / lsum[0], inv1 = 1.0f / lsum[1];
    int row0 = b * TT + q_lo;
#pragma unroll
    for (int nt = 0; nt < 16; nt++) {
        int col = h * DH + nt * 8 + 2 * (lane & 3);
        *(float2*)&O[(size_t)row0 * TD + col] =
            make_float2(oacc[nt][0] * inv0, oacc[nt][1] * inv0);
        *(float2*)&O[(size_t)(row0 + 8) * TD + col] =
            make_float2(oacc[nt][2] * inv1, oacc[nt][3] * inv1);
    }
}

// ---------------------------------------------------------------------------
extern "C" void kernel_launch(void* const* d_in, const int* in_sizes, int n_in,
                              void* d_out, int out_size)
{
    const float* X  = (const float*)d_in[0];
    const float* Wq = (const float*)d_in[1];
    const float* Wk = (const float*)d_in[2];
    const float* Wv = (const float*)d_in[3];
    const float* Wo = (const float*)d_in[4];
    float* out = (float*)d_out;

    float *Qp, *Kp, *Vp, *Ap;
    cudaGetSymbolAddress((void**)&Qp, g_Q);
    cudaGetSymbolAddress((void**)&Kp, g_K);
    cudaGetSymbolAddress((void**)&Vp, g_V);
    cudaGetSymbolAddress((void**)&Ap, g_A);
    __half *hX, *hWq, *hWk, *hWv, *hWo, *hA;
    cudaGetSymbolAddress((void**)&hX,  g_hX);
    cudaGetSymbolAddress((void**)&hWq, g_hWq); cudaGetSymbolAddress((void**)&hWk, g_hWk);
    cudaGetSymbolAddress((void**)&hWv, g_hWv); cudaGetSymbolAddress((void**)&hWo, g_hWo);
    cudaGetSymbolAddress((void**)&hA,  g_hA);
    __nv_bfloat16 *Qb, *Qs, *Kb, *Ks, *Vb, *Vs;
    cudaGetSymbolAddress((void**)&Qb, g_Qb); cudaGetSymbolAddress((void**)&Qs, g_Qs);
    cudaGetSymbolAddress((void**)&Kb, g_Kb); cudaGetSymbolAddress((void**)&Ks, g_Ks);
    cudaGetSymbolAddress((void**)&Vb, g_Vb); cudaGetSymbolAddress((void**)&Vs, g_Vs);

    cudaFuncSetAttribute(gemm_f16, cudaFuncAttributeMaxDynamicSharedMemorySize,
                         GEMM_SMEM);
    cudaFuncSetAttribute(attn_tc, cudaFuncAttributeMaxDynamicSharedMemorySize,
                         ATT_SMEM);

    const int n4w = (int)((size_t)TD * TD / 4);
    const int n4x = (int)((size_t)NTOK * TD / 4);
    conv_fp16<<<n4x / 256, 256>>>(X,  hX);
    conv_fp16<<<n4w / 256, 256>>>(Wq, hWq);
    conv_fp16<<<n4w / 256, 256>>>(Wk, hWk);
    conv_fp16<<<n4w / 256, 256>>>(Wv, hWv);
    conv_fp16<<<n4w / 256, 256>>>(Wo, hWo);

    dim3 gg(GN / BN, NTOK / BM);
    gemm_f16<<<gg, 256, GEMM_SMEM>>>(hX, hWq, Qp);
    gemm_f16<<<gg, 256, GEMM_SMEM>>>(hX, hWk, Kp);
    gemm_f16<<<gg, 256, GEMM_SMEM>>>(hX, hWv, Vp);

    const int npairs = TB * TT * TH * 64;
    rope_split<<<npairs / 256, 256>>>(Qp, Kp, Qb, Qs, Kb, Ks);
    split_bf16<<<n4x / 256, 256>>>(Vp, Vb, Vs);

    attn_tc<<<dim3(TT / 128, TB * TH), 256, ATT_SMEM>>>(
        Qb, Qs, Kb, Ks, Vb, Vs, Ap);

    conv_fp16<<<n4x / 256, 256>>>(Ap, hA);
    gemm_f16<<<gg, 256, GEMM_SMEM>>>(hA, hWo, out);
}

// round 17
// speedup vs baseline: 7.1578x; 1.0619x over previous
#include <cuda_runtime.h>
#include <cuda_bf16.h>
#include <cuda_fp16.h>
#include <cstdint>

#define TB 2
#define TT 2048
#define TD 4096
#define TH 32
#define DH 128
#define NTOK (TB*TT)

// ---------------- scratch (device globals: allocation-free rule) ------------
__device__ __half g_hX[(size_t)NTOK*TD];
__device__ __half g_hWq[(size_t)TD*TD], g_hWk[(size_t)TD*TD];
__device__ __half g_hWv[(size_t)TD*TD], g_hWo[(size_t)TD*TD];
__device__ __half g_hA[(size_t)NTOK*TD];
__device__ __half g_hV[(size_t)NTOK*TD];

__device__ __nv_bfloat16 g_Qb[(size_t)NTOK*TD], g_Qs[(size_t)NTOK*TD];
__device__ __nv_bfloat16 g_Kb[(size_t)NTOK*TD], g_Ks[(size_t)NTOK*TD];

// ---------------------------------------------------------------------------
// fp32 -> fp16 convert
// ---------------------------------------------------------------------------
__global__ __launch_bounds__(256)
void conv_fp16(const float* __restrict__ x, __half* __restrict__ h)
{
    int i = blockIdx.x * blockDim.x + threadIdx.x;
    float4 v = ((const float4*)x)[i];
    __half2* h2 = (__half2*)h;
    h2[2*i]   = __floats2half2_rn(v.x, v.y);
    h2[2*i+1] = __floats2half2_rn(v.z, v.w);
}

// ---------------------------------------------------------------------------
// shared helpers
// ---------------------------------------------------------------------------
__device__ __forceinline__ uint32_t sm_u32(const void* p) {
    uint32_t a;
    asm("{ .reg .u64 t; cvta.to.shared.u64 t, %1; cvt.u32.u64 %0, t; }"
        : "=r"(a) : "l"(p));
    return a;
}
__device__ __forceinline__ void cpasync16(uint32_t dst, const void* src) {
    asm volatile("cp.async.cg.shared.global [%0], [%1], 16;"
                 :: "r"(dst), "l"(src));
}
__device__ __forceinline__ void ldsm_x4(uint32_t* r, uint32_t addr) {
    asm volatile("ldmatrix.sync.aligned.m8n8.x4.shared.b16 {%0,%1,%2,%3}, [%4];"
                 : "=r"(r[0]), "=r"(r[1]), "=r"(r[2]), "=r"(r[3]) : "r"(addr));
}
__device__ __forceinline__ void ldsm_x4_t(uint32_t* r, uint32_t addr) {
    asm volatile("ldmatrix.sync.aligned.m8n8.x4.trans.shared.b16 {%0,%1,%2,%3}, [%4];"
                 : "=r"(r[0]), "=r"(r[1]), "=r"(r[2]), "=r"(r[3]) : "r"(addr));
}
__device__ __forceinline__ void mma_bf16(float* d, const uint32_t* a,
                                         const uint32_t* b) {
    asm volatile(
        "mma.sync.aligned.m16n8k16.row.col.f32.bf16.bf16.f32 "
        "{%0,%1,%2,%3}, {%4,%5,%6,%7}, {%8,%9}, {%0,%1,%2,%3};"
        : "+f"(d[0]), "+f"(d[1]), "+f"(d[2]), "+f"(d[3])
        : "r"(a[0]), "r"(a[1]), "r"(a[2]), "r"(a[3]), "r"(b[0]), "r"(b[1]));
}
__device__ __forceinline__ void mma_f16(float* d, const uint32_t* a,
                                        const uint32_t* b) {
    asm volatile(
        "mma.sync.aligned.m16n8k16.row.col.f32.f16.f16.f32 "
        "{%0,%1,%2,%3}, {%4,%5,%6,%7}, {%8,%9}, {%0,%1,%2,%3};"
        : "+f"(d[0]), "+f"(d[1]), "+f"(d[2]), "+f"(d[3])
        : "r"(a[0]), "r"(a[1]), "r"(a[2]), "r"(a[3]), "r"(b[0]), "r"(b[1]));
}
// bf16 big/small pack (QK path, unchanged numerics)
__device__ __forceinline__ void bsplit2(float lo, float hi,
                                        uint32_t& pb, uint32_t& ps) {
    __nv_bfloat16 bl = __float2bfloat16(lo), bh = __float2bfloat16(hi);
    __nv_bfloat162 v(bl, bh);
    pb = *(uint32_t*)&v;
    __nv_bfloat16 sl = __float2bfloat16(lo - __bfloat162float(bl));
    __nv_bfloat16 sh = __float2bfloat16(hi - __bfloat162float(bh));
    __nv_bfloat162 w(sl, sh);
    ps = *(uint32_t*)&w;
}
// fp16 big/small pack (P fragments: ~exact for [0,1])
__device__ __forceinline__ void hsplit2(float lo, float hi,
                                        uint32_t& pb, uint32_t& ps) {
    __half bl = __float2half_rn(lo), bh = __float2half_rn(hi);
    __half2 v(bl, bh);
    pb = *(uint32_t*)&v;
    __half sl = __float2half_rn(lo - __half2float(bl));
    __half sh = __float2half_rn(hi - __half2float(bh));
    __half2 w(sl, sh);
    ps = *(uint32_t*)&w;
}

// ---------------------------------------------------------------------------
// fp16 GEMM mainloop (shared): BM=BN=128, BK=64, 256 thr, warp tile 64x32,
// 3-stage cp.async pipeline. Epilogue varies per kernel below.
// ---------------------------------------------------------------------------
#define BM 128
#define BN 128
#define BK 64
#define GK 4096
#define GN 4096

#define STAGE  32768
#define OFF_A  0
#define OFF_B  16384
#define GEMM_SMEM (3*STAGE)

#define SWZ(x) ((x) ^ (((x) >> 3) & 0x70))

#define GEMM_MAINLOOP(Aptr, Bptr)                                              \
    extern __shared__ char smem[];                                             \
    const uint32_t sb = sm_u32(smem);                                          \
    const int tid = threadIdx.x, wid = tid >> 5, lane = tid & 31;              \
    const int bm = blockIdx.y * BM, bn = blockIdx.x * BN;                      \
    const int wm = (wid >> 2) * 64;                                            \
    const int wn = (wid & 3) * 32;                                             \
    const int lr = tid >> 3;                                                   \
    const int lg = (tid & 7) * 16;                                             \
    float acc[4][4][4];                                                        \
    _Pragma("unroll")                                                          \
    for (int i = 0; i < 4; i++)                                                \
        _Pragma("unroll")                                                      \
        for (int j = 0; j < 4; j++)                                            \
            _Pragma("unroll")                                                  \
            for (int q = 0; q < 4; q++) acc[i][j][q] = 0.f;                    \
    const int nIter = GK / BK;                                                 \
    auto load_stage = [&](int s, int c) {                                      \
        const int kc = c * BK;                                                 \
        uint32_t st = sb + s * STAGE;                                          \
        _Pragma("unroll")                                                      \
        for (int t = 0; t < 4; t++) {                                          \
            int r = lr + t * 32;                                               \
            uint32_t so = SWZ((uint32_t)(r * 128) + lg);                       \
            cpasync16(st + OFF_A + so,                                         \
                      (const char*)(Aptr + (size_t)(bm + r) * GK + kc) + lg);  \
            cpasync16(st + OFF_B + so,                                         \
                      (const char*)(Bptr + (size_t)(bn + r) * GK + kc) + lg);  \
        }                                                                      \
        asm volatile("cp.async.commit_group;");                                \
    };                                                                         \
    load_stage(0, 0);                                                          \
    load_stage(1, 1);                                                          \
    const int a_row = (lane & 7) + ((lane >> 3) & 1) * 8;                      \
    const int a_kh  = ((lane >> 4) & 1) * 16;                                  \
    const int b_row = (lane & 7) + ((lane >> 4) & 1) * 8;                      \
    const int b_kh  = ((lane >> 3) & 1) * 16;                                  \
    for (int c = 0; c < nIter; c++) {                                          \
        if (c + 1 < nIter) asm volatile("cp.async.wait_group 1;");             \
        else               asm volatile("cp.async.wait_group 0;");             \
        __syncthreads();                                                       \
        if (c + 2 < nIter) load_stage((c + 2) % 3, c + 2);                     \
        uint32_t st = sb + (c % 3) * STAGE;                                    \
        _Pragma("unroll")                                                      \
        for (int ks = 0; ks < 4; ks++) {                                       \
            const uint32_t kb = ks * 32;                                       \
            uint32_t af[4][4], bfr[2][4];                                      \
            _Pragma("unroll")                                                  \
            for (int i = 0; i < 4; i++) {                                      \
                int row = wm + i * 16 + a_row;                                 \
                ldsm_x4(af[i], st + OFF_A + SWZ((uint32_t)(row*128)+kb+a_kh)); \
            }                                                                  \
            _Pragma("unroll")                                                  \
            for (int jp = 0; jp < 2; jp++) {                                   \
                int row = wn + jp * 16 + b_row;                                \
                ldsm_x4(bfr[jp], st + OFF_B + SWZ((uint32_t)(row*128)+kb+b_kh));\
            }                                                                  \
            _Pragma("unroll")                                                  \
            for (int i = 0; i < 4; i++)                                        \
                _Pragma("unroll")                                              \
                for (int j = 0; j < 4; j++)                                    \
                    mma_f16(acc[i][j], af[i], &bfr[j >> 1][(j & 1) * 2]);      \
        }                                                                      \
    }                                                                          \
    const int g  = lane >> 2;                                                  \
    const int tq = (lane & 3) * 2;

// Plain GEMM -> fp32 C (final Wo projection)
__global__ __launch_bounds__(256, 1)
void gemm_f16(const __half* __restrict__ A, const __half* __restrict__ Bf,
              float* __restrict__ C)
{
    GEMM_MAINLOOP(A, Bf)
#pragma unroll
    for (int i = 0; i < 4; i++) {
        int row = bm + wm + i * 16 + g;
#pragma unroll
        for (int j = 0; j < 4; j++) {
            int col = bn + wn + j * 8 + tq;
            *(float2*)&C[(size_t)row * GN + col] =
                make_float2(acc[i][j][0], acc[i][j][1]);
            *(float2*)&C[(size_t)(row + 8) * GN + col] =
                make_float2(acc[i][j][2], acc[i][j][3]);
        }
    }
}

// GEMM -> fp16 C (V projection)
__global__ __launch_bounds__(256, 1)
void gemm_h16(const __half* __restrict__ A, const __half* __restrict__ Bf,
              __half* __restrict__ C)
{
    GEMM_MAINLOOP(A, Bf)
#pragma unroll
    for (int i = 0; i < 4; i++) {
        int row = bm + wm + i * 16 + g;
#pragma unroll
        for (int j = 0; j < 4; j++) {
            int col = bn + wn + j * 8 + tq;
            *(__half2*)&C[(size_t)row * GN + col] =
                __floats2half2_rn(acc[i][j][0], acc[i][j][1]);
            *(__half2*)&C[(size_t)(row + 8) * GN + col] =
                __floats2half2_rn(acc[i][j][2], acc[i][j][3]);
        }
    }
}

// GEMM -> RoPE -> bf16 big/small split (Q and K projections).
// Thread cols (col, col+1), col even == head pair (2j, 2j+1). scale=1/sqrt(Dh)
// for Q, 1.0 for K.
__global__ __launch_bounds__(256, 1)
void gemm_rope(const __half* __restrict__ A, const __half* __restrict__ Bf,
               __nv_bfloat16* __restrict__ Ob, __nv_bfloat16* __restrict__ Os,
               float scale)
{
    GEMM_MAINLOOP(A, Bf)
#pragma unroll
    for (int j = 0; j < 4; j++) {
        int col = bn + wn + j * 8 + tq;
        int d   = col & (DH - 1);
        int jj  = d >> 1;
        int m   = (jj < 32) ? 2 * jj : 2 * jj - 64;
        float freq = __expf(-(float)m * (9.903487552536127f / 64.0f));
#pragma unroll
        for (int i = 0; i < 4; i++) {
            int row = bm + wm + i * 16 + g;
#pragma unroll
            for (int hh = 0; hh < 2; hh++) {
                int r  = row + hh * 8;
                int t  = r & (TT - 1);
                float sn, cs;
                sincosf((float)t * freq, &sn, &cs);
                float x1 = acc[i][j][2 * hh], x2 = acc[i][j][2 * hh + 1];
                float r1 = (x1 * cs - x2 * sn) * scale;
                float r2 = (x1 * sn + x2 * cs) * scale;
                uint32_t pb, ps;
                bsplit2(r1, r2, pb, ps);
                *(uint32_t*)&Ob[(size_t)r * GN + col] = pb;
                *(uint32_t*)&Os[(size_t)r * GN + col] = ps;
            }
        }
    }
}

// ---------------------------------------------------------------------------
// Tensor-core flash attention (causal). QK^T: bf16x3. P*V: fp16 2-term
// (P big/small x V single fp16). 2-stage K/V pipeline. Output written as fp16.
// SMEM: Q 64KB | 2 stages x (KB 16K | KS 16K | VF 16K) = 160KB.
// ---------------------------------------------------------------------------
#define AOFF_QB 0
#define AOFF_QS 32768
#define AOFF_KV 65536
#define KV_KB 0
#define KV_KS 16384
#define KV_VF 32768
#define KV_STAGE 49152
#define ATT_SMEM (65536 + 2*KV_STAGE)   // 163840

#define SWZ256(r, c16) ((uint32_t)((r) * 256 + (((c16) ^ ((r) & 7)) << 4)))

__global__ __launch_bounds__(256, 1)
void attn_tc(const __nv_bfloat16* __restrict__ Qb, const __nv_bfloat16* __restrict__ Qs,
             const __nv_bfloat16* __restrict__ Kb, const __nv_bfloat16* __restrict__ Ks,
             const __half* __restrict__ Vf, __half* __restrict__ O)
{
    extern __shared__ char smem[];
    const uint32_t sb = sm_u32(smem);
    const int tid = threadIdx.x, wid = tid >> 5, lane = tid & 31;
    const int qt = blockIdx.x;
    const int bh = blockIdx.y;
    const int b  = bh >> 5, h = bh & 31;
    const size_t head = (size_t)b * TT * TD + (size_t)h * DH;
    const int wm = wid * 16;

#pragma unroll
    for (int i = 0; i < 8; i++) {
        int g = tid + i * 256;
        int r = g >> 4, c = g & 15;
        const char* src = (const char*)(Qb + head + (size_t)(qt * 128 + r) * TD) + c * 16;
        const char* srs = (const char*)(Qs + head + (size_t)(qt * 128 + r) * TD) + c * 16;
        cpasync16(sb + AOFF_QB + SWZ256(r, c), src);
        cpasync16(sb + AOFF_QS + SWZ256(r, c), srs);
    }
    asm volatile("cp.async.commit_group;");

    auto load_kv = [&](int s, int kt) {
        uint32_t base = sb + AOFF_KV + (uint32_t)s * KV_STAGE;
#pragma unroll
        for (int i = 0; i < 4; i++) {
            int g = tid + i * 256;
            int r = g >> 4, c = g & 15;
            size_t grow = head + (size_t)(kt * 64 + r) * TD;
            uint32_t so = SWZ256(r, c);
            cpasync16(base + KV_KB + so, (const char*)(Kb + grow) + c * 16);
            cpasync16(base + KV_KS + so, (const char*)(Ks + grow) + c * 16);
            cpasync16(base + KV_VF + so, (const char*)(Vf + grow) + c * 16);
        }
        asm volatile("cp.async.commit_group;");
    };

    const int a_row = (lane & 7) + ((lane >> 3) & 1) * 8;
    const int a_k16 = (lane >> 4) & 1;
    const int b_row = (lane & 7) + ((lane >> 4) & 1) * 8;
    const int b_k16 = (lane >> 3) & 1;
    const int v_row = (lane & 7) + ((lane >> 3) & 1) * 8;
    const int v_c16 = (lane >> 4) & 1;

    float oacc[16][4];
#pragma unroll
    for (int nt = 0; nt < 16; nt++)
#pragma unroll
        for (int q = 0; q < 4; q++) oacc[nt][q] = 0.f;
    float mrow[2] = {-1e30f, -1e30f};
    float lsum[2] = {0.f, 0.f};

    const int q_lo = qt * 128 + wm + (lane >> 2);

    const int nkt = 2 * qt + 2;
    load_kv(0, 0);

    for (int kt = 0; kt < nkt; kt++) {
        const int st = kt & 1;
        if (kt + 1 < nkt) {
            load_kv(st ^ 1, kt + 1);
            asm volatile("cp.async.wait_group 1;");
        } else {
            asm volatile("cp.async.wait_group 0;");
        }
        __syncthreads();

        const uint32_t kvb = sb + AOFF_KV + (uint32_t)st * KV_STAGE;

        // ---- S = Q K^T (bf16x3) ----
        float sacc[8][4];
#pragma unroll
        for (int s8 = 0; s8 < 8; s8++)
#pragma unroll
            for (int q = 0; q < 4; q++) sacc[s8][q] = 0.f;

#pragma unroll
        for (int dc = 0; dc < 8; dc++) {
            uint32_t qb_[4], qs_[4];
            uint32_t qoff = SWZ256(wm + a_row, dc * 2 + a_k16);
            ldsm_x4(qb_, sb + AOFF_QB + qoff);
            ldsm_x4(qs_, sb + AOFF_QS + qoff);
#pragma unroll
            for (int ntp = 0; ntp < 4; ntp++) {
                uint32_t kb_[4], ks_[4];
                uint32_t koff = SWZ256(ntp * 16 + b_row, dc * 2 + b_k16);
                ldsm_x4(kb_, kvb + KV_KB + koff);
                ldsm_x4(ks_, kvb + KV_KS + koff);
#pragma unroll
                for (int j = 0; j < 2; j++) {
                    float* d = sacc[ntp * 2 + j];
                    mma_bf16(d, qb_, &kb_[2 * j]);
                    mma_bf16(d, qb_, &ks_[2 * j]);
                    mma_bf16(d, qs_, &kb_[2 * j]);
                }
            }
        }

        // ---- causal mask ----
        if (kt >= 2 * qt) {
#pragma unroll
            for (int s8 = 0; s8 < 8; s8++) {
                int key0 = kt * 64 + s8 * 8 + 2 * (lane & 3);
#pragma unroll
                for (int e = 0; e < 2; e++) {
                    if (key0 + e > q_lo)     sacc[s8][e]     = -1e30f;
                    if (key0 + e > q_lo + 8) sacc[s8][2 + e] = -1e30f;
                }
            }
        }

        // ---- online softmax ----
        float alpha[2];
#pragma unroll
        for (int hh = 0; hh < 2; hh++) {
            float mx = -1e30f;
#pragma unroll
            for (int s8 = 0; s8 < 8; s8++)
                mx = fmaxf(mx, fmaxf(sacc[s8][2 * hh], sacc[s8][2 * hh + 1]));
            mx = fmaxf(mx, __shfl_xor_sync(0xffffffffu, mx, 1));
            mx = fmaxf(mx, __shfl_xor_sync(0xffffffffu, mx, 2));
            float mn = fmaxf(mrow[hh], mx);
            alpha[hh] = __expf(mrow[hh] - mn);
            mrow[hh] = mn;
            float rs = 0.f;
#pragma unroll
            for (int s8 = 0; s8 < 8; s8++) {
                float p0 = __expf(sacc[s8][2 * hh]     - mn);
                float p1 = __expf(sacc[s8][2 * hh + 1] - mn);
                sacc[s8][2 * hh] = p0; sacc[s8][2 * hh + 1] = p1;
                rs += p0 + p1;
            }
            rs += __shfl_xor_sync(0xffffffffu, rs, 1);
            rs += __shfl_xor_sync(0xffffffffu, rs, 2);
            lsum[hh] = lsum[hh] * alpha[hh] + rs;
        }
#pragma unroll
        for (int nt = 0; nt < 16; nt++) {
            oacc[nt][0] *= alpha[0]; oacc[nt][1] *= alpha[0];
            oacc[nt][2] *= alpha[1]; oacc[nt][3] *= alpha[1];
        }

        // ---- O += P V  (P fp16 big/small x V fp16 single: 2 mma terms) ----
#pragma unroll
        for (int kc = 0; kc < 4; kc++) {
            uint32_t pb[4], ps[4];
            hsplit2(sacc[2*kc][0],   sacc[2*kc][1],   pb[0], ps[0]);
            hsplit2(sacc[2*kc][2],   sacc[2*kc][3],   pb[1], ps[1]);
            hsplit2(sacc[2*kc+1][0], sacc[2*kc+1][1], pb[2], ps[2]);
            hsplit2(sacc[2*kc+1][2], sacc[2*kc+1][3], pb[3], ps[3]);
#pragma unroll
            for (int np = 0; np < 8; np++) {
                uint32_t vf_[4];
                uint32_t voff = SWZ256(kc * 16 + v_row, np * 2 + v_c16);
                ldsm_x4_t(vf_, kvb + KV_VF + voff);
#pragma unroll
                for (int j = 0; j < 2; j++) {
                    float* d = oacc[np * 2 + j];
                    mma_f16(d, pb, &vf_[2 * j]);
                    mma_f16(d, ps, &vf_[2 * j]);
                }
            }
        }
        __syncthreads();
    }

    // ---- epilogue: O /= l, write fp16 [b,t][h*128+d] ----
    float inv0 = 1.0f / lsum[0], inv1 = 1.0f / lsum[1];
    int row0 = b * TT + q_lo;
#pragma unroll
    for (int nt = 0; nt < 16; nt++) {
        int col = h * DH + nt * 8 + 2 * (lane & 3);
        *(__half2*)&O[(size_t)row0 * TD + col] =
            __floats2half2_rn(oacc[nt][0] * inv0, oacc[nt][1] * inv0);
        *(__half2*)&O[(size_t)(row0 + 8) * TD + col] =
            __floats2half2_rn(oacc[nt][2] * inv1, oacc[nt][3] * inv1);
    }
}

// ---------------------------------------------------------------------------
extern "C" void kernel_launch(void* const* d_in, const int* in_sizes, int n_in,
                              void* d_out, int out_size)
{
    const float* X  = (const float*)d_in[0];
    const float* Wq = (const float*)d_in[1];
    const float* Wk = (const float*)d_in[2];
    const float* Wv = (const float*)d_in[3];
    const float* Wo = (const float*)d_in[4];
    float* out = (float*)d_out;

    __half *hX, *hWq, *hWk, *hWv, *hWo, *hA, *hV;
    cudaGetSymbolAddress((void**)&hX,  g_hX);
    cudaGetSymbolAddress((void**)&hWq, g_hWq); cudaGetSymbolAddress((void**)&hWk, g_hWk);
    cudaGetSymbolAddress((void**)&hWv, g_hWv); cudaGetSymbolAddress((void**)&hWo, g_hWo);
    cudaGetSymbolAddress((void**)&hA,  g_hA);  cudaGetSymbolAddress((void**)&hV,  g_hV);
    __nv_bfloat16 *Qb, *Qs, *Kb, *Ks;
    cudaGetSymbolAddress((void**)&Qb, g_Qb); cudaGetSymbolAddress((void**)&Qs, g_Qs);
    cudaGetSymbolAddress((void**)&Kb, g_Kb); cudaGetSymbolAddress((void**)&Ks, g_Ks);

    cudaFuncSetAttribute(gemm_f16, cudaFuncAttributeMaxDynamicSharedMemorySize,
                         GEMM_SMEM);
    cudaFuncSetAttribute(gemm_h16, cudaFuncAttributeMaxDynamicSharedMemorySize,
                         GEMM_SMEM);
    cudaFuncSetAttribute(gemm_rope, cudaFuncAttributeMaxDynamicSharedMemorySize,
                         GEMM_SMEM);
    cudaFuncSetAttribute(attn_tc, cudaFuncAttributeMaxDynamicSharedMemorySize,
                         ATT_SMEM);

    const int n4w = (int)((size_t)TD * TD / 4);
    const int n4x = (int)((size_t)NTOK * TD / 4);
    conv_fp16<<<n4x / 256, 256>>>(X,  hX);
    conv_fp16<<<n4w / 256, 256>>>(Wq, hWq);
    conv_fp16<<<n4w / 256, 256>>>(Wk, hWk);
    conv_fp16<<<n4w / 256, 256>>>(Wv, hWv);
    conv_fp16<<<n4w / 256, 256>>>(Wo, hWo);

    dim3 gg(GN / BN, NTOK / BM);
    gemm_rope<<<gg, 256, GEMM_SMEM>>>(hX, hWq, Qb, Qs, 0.08838834764831845f);
    gemm_rope<<<gg, 256, GEMM_SMEM>>>(hX, hWk, Kb, Ks, 1.0f);
    gemm_h16<<<gg, 256, GEMM_SMEM>>>(hX, hWv, hV);

    attn_tc<<<dim3(TT / 128, TB * TH), 256, ATT_SMEM>>>(
        Qb, Qs, Kb, Ks, hV, hA);

    gemm_f16<<<gg, 256, GEMM_SMEM>>>(hA, hWo, out);
}